// round 13
// baseline (speedup 1.0000x reference)
#include <cuda_runtime.h>
#include <cuda_bf16.h>
#include <math.h>
#include <stdint.h>

#define CB 2
#define CS 2048
#define CE 1024
#define CH 16
#define CD 64
#define CM (CB*CS)          // 4096 tokens
#define YAT_EPS 1e-5f

__device__ __forceinline__ uint32_t smem_u32(const void* p) {
    uint32_t a;
    asm("{ .reg .u64 t; cvta.to.shared.u64 t, %1; cvt.u32.u64 %0, t; }" : "=r"(a) : "l"(p));
    return a;
}

// ---- mma.sync / ldmatrix / cp.async helpers (portable to non-'a' sm_103) ----
__device__ __forceinline__ void ldsm_x4(uint32_t* r, uint32_t addr) {
    asm volatile("ldmatrix.sync.aligned.m8n8.x4.shared.b16 {%0,%1,%2,%3}, [%4];"
        : "=r"(r[0]), "=r"(r[1]), "=r"(r[2]), "=r"(r[3]) : "r"(addr));
}
__device__ __forceinline__ void ldsm_x4_t(uint32_t* r, uint32_t addr) {
    asm volatile("ldmatrix.sync.aligned.m8n8.x4.trans.shared.b16 {%0,%1,%2,%3}, [%4];"
        : "=r"(r[0]), "=r"(r[1]), "=r"(r[2]), "=r"(r[3]) : "r"(addr));
}
__device__ __forceinline__ void mma_bf16(float* c, const uint32_t* a, const uint32_t* b) {
    asm volatile(
        "mma.sync.aligned.m16n8k16.row.col.f32.bf16.bf16.f32 "
        "{%0,%1,%2,%3}, {%4,%5,%6,%7}, {%8,%9}, {%0,%1,%2,%3};"
        : "+f"(c[0]), "+f"(c[1]), "+f"(c[2]), "+f"(c[3])
        : "r"(a[0]), "r"(a[1]), "r"(a[2]), "r"(a[3]), "r"(b[0]), "r"(b[1]));
}
__device__ __forceinline__ uint32_t prmt7632(uint32_t a, uint32_t b) {
    uint32_t r; asm("prmt.b32 %0, %1, %2, 0x7632;" : "=r"(r) : "r"(a), "r"(b)); return r;
}
__device__ __forceinline__ uint32_t pkbf16x2(float lo, float hi) {
    uint32_t r; asm("cvt.rn.bf16x2.f32 %0, %1, %2;" : "=r"(r) : "f"(hi), "f"(lo)); return r;
}
__device__ __forceinline__ void cpasync16(uint32_t dst, const void* src) {
    asm volatile("cp.async.cg.shared.global [%0], [%1], 16;" :: "r"(dst), "l"(src));
}
#define CP_COMMIT() asm volatile("cp.async.commit_group;" ::: "memory")
#define CP_WAIT(n)  asm volatile("cp.async.wait_group %0;" :: "n"(n) : "memory")

// ---- Scratch (__device__ globals; allocation-free rule) ----
__device__ __nv_bfloat16 g_xh[(size_t)CM*CE], g_xl[(size_t)CM*CE];
__device__ __nv_bfloat16 g_oh[(size_t)CM*CE], g_ol[(size_t)CM*CE];
__device__ __nv_bfloat16 g_wqh[(size_t)CE*CE], g_wql[(size_t)CE*CE];
__device__ __nv_bfloat16 g_wkh[(size_t)CE*CE], g_wkl[(size_t)CE*CE];
__device__ __nv_bfloat16 g_wvh[(size_t)CE*CE], g_wvl[(size_t)CE*CE];
__device__ __nv_bfloat16 g_woh[(size_t)CE*CE], g_wol[(size_t)CE*CE];
__device__ __nv_bfloat16 g_aqh[(size_t)CM*CE], g_aql[(size_t)CM*CE];
__device__ __nv_bfloat16 g_akh[(size_t)CM*CE], g_akl[(size_t)CM*CE];
__device__ __nv_bfloat16 g_avh[(size_t)CM*CE], g_avl[(size_t)CM*CE];
__device__ float g_qn[(size_t)CH*CM];
__device__ float g_kn[(size_t)CH*CM];

// ---------------------------------------------------------------------------
struct SplitJob { const float* x; __nv_bfloat16* hi; __nv_bfloat16* lo; };

__global__ __launch_bounds__(256) void split_bf16_multi(
    SplitJob j0, SplitJob j1, SplitJob j2, SplitJob j3, int n4)
{
    int i = blockIdx.x * blockDim.x + threadIdx.x;
    if (i >= n4) return;
    SplitJob j = (blockIdx.y == 0) ? j0 : (blockIdx.y == 1) ? j1 : (blockIdx.y == 2) ? j2 : j3;
    float4 v = ((const float4*)j.x)[i];
    union { __nv_bfloat16 b[4]; uint2 u; } H, L;
    float a[4] = {v.x, v.y, v.z, v.w};
#pragma unroll
    for (int jj = 0; jj < 4; jj++) {
        __nv_bfloat16 h = __float2bfloat16(a[jj]);
        H.b[jj] = h;
        L.b[jj] = __float2bfloat16(a[jj] - __bfloat162float(h));
    }
    ((uint2*)j.hi)[i] = H.u;
    ((uint2*)j.lo)[i] = L.u;
}

// ---------------------------------------------------------------------------
// C = A @ B^T + bias, mma.sync bf16 3-split.
// CTA tile 128x256, warp tile 64x64 (8 warps, 2x4). 85 B/mma vs crossbar.
// ---------------------------------------------------------------------------
#define LDA 40
#define SA_H 0
#define SA_L 10240
#define SB_H 20480
#define SB_L 40960
#define STG_B 61440
#define HG_SMEM (2*STG_B)      // 122880 B

struct GemmJob {
    const __nv_bfloat16 *Ah, *Al, *Bh, *Bl;
    const float* bias;
    float* C;
    __nv_bfloat16 *Chi, *Clo;
    float* norm;
};

__global__ void __launch_bounds__(256, 1) hgemm_nt_3split(
    GemmJob j0, GemmJob j1, GemmJob j2, int M, int N, int K)
{
    extern __shared__ __nv_bfloat16 smem[];
    const uint32_t uS = smem_u32(smem);
    const GemmJob jb = (blockIdx.z == 0) ? j0 : (blockIdx.z == 1) ? j1 : j2;

    const int tid = threadIdx.x, lane = tid & 31, wid = tid >> 5;
    const int wm = wid >> 2, wn = wid & 3;          // 2 x 4 warps, 64x64 tiles
    const int row0 = blockIdx.y * 128, col0 = blockIdx.x * 256;

    float acc[4][8][4];
#pragma unroll
    for (int i = 0; i < 4; i++)
#pragma unroll
        for (int j = 0; j < 8; j++)
#pragma unroll
            for (int f = 0; f < 4; f++) acc[i][j][f] = 0.0f;

    const int a_row = lane & 15, a_kg = lane >> 4;
    const int b_row = ((lane >> 4) & 1) * 8 + (lane & 7);
    const int b_kg  = (lane >> 3) & 1;

    const int gr = tid >> 2;             // 0..63
    const int gc = (tid & 3) * 8;        // 0,8,16,24

    const int NT = K / 32;

    auto load_st = [&](int s, int t) {
        const int k0 = t * 32;
        const uint32_t base = uS + s * STG_B;
#pragma unroll
        for (int pp = 0; pp < 2; pp++) {
            int r = pp * 64 + gr;
            uint32_t doff = (uint32_t)(r * LDA + gc) * 2;
            size_t ga = (size_t)(row0 + r) * K + k0 + gc;
            cpasync16(base + SA_H + doff, &jb.Ah[ga]);
            cpasync16(base + SA_L + doff, &jb.Al[ga]);
        }
#pragma unroll
        for (int pp = 0; pp < 4; pp++) {
            int r = pp * 64 + gr;
            uint32_t doff = (uint32_t)(r * LDA + gc) * 2;
            size_t gb = (size_t)(col0 + r) * K + k0 + gc;
            cpasync16(base + SB_H + doff, &jb.Bh[gb]);
            cpasync16(base + SB_L + doff, &jb.Bl[gb]);
        }
    };

    load_st(0, 0);
    CP_COMMIT();

    for (int t = 0; t < NT; t++) {
        CP_WAIT(0);
        __syncthreads();
        if (t + 1 < NT) {
            load_st((t + 1) & 1, t + 1);
            CP_COMMIT();
        }
        const uint32_t st = uS + (t & 1) * STG_B;

#pragma unroll
        for (int kk = 0; kk < 2; kk++) {
            const uint32_t aoff = ((wm * 64 + a_row) * LDA + kk * 16 + a_kg * 8) * 2;
            uint32_t bh_f[8][2], bl_f[8][2], af[4][4];
#pragma unroll
            for (int nb = 0; nb < 4; nb++) {
                const uint32_t boff = ((wn * 64 + nb * 16 + b_row) * LDA + kk * 16 + b_kg * 8) * 2;
                uint32_t tt[4];
                ldsm_x4(tt, st + SB_H + boff);
                bh_f[2 * nb][0] = tt[0]; bh_f[2 * nb][1] = tt[1];
                bh_f[2 * nb + 1][0] = tt[2]; bh_f[2 * nb + 1][1] = tt[3];
                ldsm_x4(tt, st + SB_L + boff);
                bl_f[2 * nb][0] = tt[0]; bl_f[2 * nb][1] = tt[1];
                bl_f[2 * nb + 1][0] = tt[2]; bl_f[2 * nb + 1][1] = tt[3];
            }
#pragma unroll
            for (int mi = 0; mi < 4; mi++)
                ldsm_x4(af[mi], st + SA_H + aoff + mi * 16 * LDA * 2);
#pragma unroll
            for (int mi = 0; mi < 4; mi++)
#pragma unroll
                for (int ni = 0; ni < 8; ni++)
                    mma_bf16(acc[mi][ni], af[mi], bh_f[ni]);
#pragma unroll
            for (int mi = 0; mi < 4; mi++)
#pragma unroll
                for (int ni = 0; ni < 8; ni++)
                    mma_bf16(acc[mi][ni], af[mi], bl_f[ni]);
#pragma unroll
            for (int mi = 0; mi < 4; mi++)
                ldsm_x4(af[mi], st + SA_L + aoff + mi * 16 * LDA * 2);
#pragma unroll
            for (int mi = 0; mi < 4; mi++)
#pragma unroll
                for (int ni = 0; ni < 8; ni++)
                    mma_bf16(acc[mi][ni], af[mi], bh_f[ni]);
        }
    }
    __syncthreads();

    const int erow = lane >> 2, ecol = (lane & 3) * 2;
    const int tg = lane & 3;
    const int hh = (col0 + wn * 64) >> 6;     // warp's 64 N-cols == one head
#pragma unroll
    for (int mi = 0; mi < 4; mi++) {
        int rg = row0 + wm * 64 + mi * 16 + erow;
        float s0 = 0.0f, s1 = 0.0f;
#pragma unroll
        for (int ni = 0; ni < 8; ni++) {
            int cg = col0 + wn * 64 + ni * 8 + ecol;
            float2 bb = *(const float2*)&jb.bias[cg];
            float o00 = acc[mi][ni][0] + bb.x, o01 = acc[mi][ni][1] + bb.y;
            float o10 = acc[mi][ni][2] + bb.x, o11 = acc[mi][ni][3] + bb.y;
            s0 += o00 * o00 + o01 * o01;
            s1 += o10 * o10 + o11 * o11;
            size_t i0 = (size_t)rg * N + cg, i1 = (size_t)(rg + 8) * N + cg;
            if (jb.C) {
                *(float2*)&jb.C[i0] = make_float2(o00, o01);
                *(float2*)&jb.C[i1] = make_float2(o10, o11);
            }
            if (jb.Chi) {
                __nv_bfloat16 h00 = __float2bfloat16(o00), h01 = __float2bfloat16(o01);
                __nv_bfloat16 h10 = __float2bfloat16(o10), h11 = __float2bfloat16(o11);
                *(__nv_bfloat162*)&jb.Chi[i0] = __nv_bfloat162(h00, h01);
                *(__nv_bfloat162*)&jb.Chi[i1] = __nv_bfloat162(h10, h11);
                *(__nv_bfloat162*)&jb.Clo[i0] = __nv_bfloat162(
                    __float2bfloat16(o00 - __bfloat162float(h00)),
                    __float2bfloat16(o01 - __bfloat162float(h01)));
                *(__nv_bfloat162*)&jb.Clo[i1] = __nv_bfloat162(
                    __float2bfloat16(o10 - __bfloat162float(h10)),
                    __float2bfloat16(o11 - __bfloat162float(h11)));
            }
        }
        if (jb.norm) {
            // row's head-norm lives entirely in this warp: reduce 4 lanes, store
#pragma unroll
            for (int off = 1; off <= 2; off <<= 1) {
                s0 += __shfl_xor_sync(0xffffffffu, s0, off);
                s1 += __shfl_xor_sync(0xffffffffu, s1, off);
            }
            if (tg == 0) {
                jb.norm[(size_t)hh * CM + rg] = s0;
                jb.norm[(size_t)hh * CM + rg + 8] = s1;
            }
        }
    }
}

// ---------------------------------------------------------------------------
// YAT flash attention (unchanged R12): 256 q-rows/CTA, 32 q-rows/warp.
// ---------------------------------------------------------------------------
#define LDS 72
#define AQ_EL 18432
#define KV_EL 18432
#define ATTN_SMEM ((2*AQ_EL + 2*KV_EL)*2 + 512 + 128)   // 148096 B

__global__ void __launch_bounds__(256, 1) yat_attn_mma(
    const __nv_bfloat16* __restrict__ Qhm, const __nv_bfloat16* __restrict__ Qlm,
    const __nv_bfloat16* __restrict__ Khm, const __nv_bfloat16* __restrict__ Klm,
    const __nv_bfloat16* __restrict__ Vhm, const __nv_bfloat16* __restrict__ Vlm,
    const float* __restrict__ qn, const float* __restrict__ kn,
    __nv_bfloat16* __restrict__ Ohm, __nv_bfloat16* __restrict__ Olm,
    const float* __restrict__ alphap)
{
    extern __shared__ __nv_bfloat16 sb[];
    const uint32_t uS = smem_u32(sb);
    const uint32_t uQh = uS, uQl = uS + AQ_EL * 2;
    const uint32_t uKV = uS + 2 * AQ_EL * 2;
    const uint32_t uKN = uS + (2 * AQ_EL + 2 * KV_EL) * 2;

    const int tid = threadIdx.x, lane = tid & 31, w = tid >> 5;
    const int g = lane >> 2, tg = lane & 3;
    const int b = blockIdx.z, h = blockIdx.y;
    const int q0 = blockIdx.x * 256;
    const size_t tokq = (size_t)b * CS + q0;

    const float scale = powf(8.0f / logf(65.0f), alphap[0]);

    {
        int c8 = tid & 7;
        int rb = tid >> 3;
#pragma unroll
        for (int i = 0; i < 8; i++) {
            int r = rb + i * 32;
            size_t gq = (tokq + r) * CE + h * CD + c8 * 8;
            *(uint4*)&sb[r * LDS + c8 * 8] = *(const uint4*)&Qhm[gq];
            *(uint4*)&sb[AQ_EL + r * LDS + c8 * 8] = *(const uint4*)&Qlm[gq];
        }
    }

    float sq[2][2];
#pragma unroll
    for (int mi = 0; mi < 2; mi++) {
        sq[mi][0] = qn[(size_t)h * CM + tokq + w * 32 + mi * 16 + g];
        sq[mi][1] = qn[(size_t)h * CM + tokq + w * 32 + mi * 16 + g + 8];
    }

    float l[2][2] = {{0.f, 0.f}, {0.f, 0.f}};
    float accO[2][8][4];
#pragma unroll
    for (int mi = 0; mi < 2; mi++)
#pragma unroll
        for (int i = 0; i < 8; i++)
#pragma unroll
            for (int j = 0; j < 4; j++) accO[mi][i][j] = 0.0f;

    const int a_row = lane & 15, a_kg = lane >> 4;
    const int b_row = ((lane >> 4) & 1) * 8 + (lane & 7);
    const int b_kg  = (lane >> 3) & 1;

    auto load_kv = [&](int stg, int t) {
        int r = tid >> 2, c2 = (tid & 3) * 2;
        size_t gk = ((size_t)b * CS + t * 64 + r) * CE + h * CD;
        const uint32_t sbase = uKV + (uint32_t)stg * KV_EL * 2u;
#pragma unroll
        for (int u = 0; u < 2; u++) {
            int cc = (c2 + u) * 8;
            uint32_t doff = (uint32_t)(r * LDS + cc) * 2;
            cpasync16(sbase + 0u * 9216u + doff, &Khm[gk + cc]);
            cpasync16(sbase + 1u * 9216u + doff, &Klm[gk + cc]);
            cpasync16(sbase + 2u * 9216u + doff, &Vhm[gk + cc]);
            cpasync16(sbase + 3u * 9216u + doff, &Vlm[gk + cc]);
        }
        if (tid < 16)
            cpasync16(uKN + (uint32_t)stg * 256u + tid * 16,
                      &kn[(size_t)h * CM + b * CS + t * 64 + tid * 4]);
    };

    load_kv(0, 0);
    CP_COMMIT();

    const int NT = CS / 64;
    for (int t = 0; t < NT; t++) {
        CP_WAIT(0);
        __syncthreads();
        if (t + 1 < NT) {
            load_kv((t + 1) & 1, t + 1);
            CP_COMMIT();
        }
        const uint32_t kb = uKV + (uint32_t)(t & 1) * KV_EL * 2u;
        const uint32_t uKh = kb, uKl = kb + 9216u, uVh = kb + 18432u, uVl = kb + 27648u;
        const float* skn = (const float*)((const char*)sb + (2 * AQ_EL + 2 * KV_EL) * 2 + (t & 1) * 256);

        float sS[2][8][4];
#pragma unroll
        for (int mi = 0; mi < 2; mi++)
#pragma unroll
            for (int i = 0; i < 8; i++)
#pragma unroll
                for (int j = 0; j < 4; j++) sS[mi][i][j] = 0.0f;

#pragma unroll
        for (int kk = 0; kk < 4; kk++) {
            uint32_t ah[2][4], al[2][4];
#pragma unroll
            for (int mi = 0; mi < 2; mi++) {
                const uint32_t aoff = ((w * 32 + mi * 16 + a_row) * LDS + kk * 16 + a_kg * 8) * 2;
                ldsm_x4(ah[mi], uQh + aoff);
                ldsm_x4(al[mi], uQl + aoff);
            }
#pragma unroll
            for (int nb = 0; nb < 4; nb++) {
                const uint32_t boff = ((nb * 16 + b_row) * LDS + kk * 16 + b_kg * 8) * 2;
                uint32_t th[4], tl[4];
                ldsm_x4(th, uKh + boff);
                ldsm_x4(tl, uKl + boff);
#pragma unroll
                for (int mi = 0; mi < 2; mi++) {
                    mma_bf16(sS[mi][2 * nb],     ah[mi], th);
                    mma_bf16(sS[mi][2 * nb + 1], ah[mi], th + 2);
                    mma_bf16(sS[mi][2 * nb],     ah[mi], tl);
                    mma_bf16(sS[mi][2 * nb + 1], ah[mi], tl + 2);
                    mma_bf16(sS[mi][2 * nb],     al[mi], th);
                    mma_bf16(sS[mi][2 * nb + 1], al[mi], th + 2);
                }
            }
        }

#pragma unroll
        for (int mi = 0; mi < 2; mi++) {
#pragma unroll
            for (int ni = 0; ni < 8; ni++) {
                int col = ni * 8 + tg * 2;
                float k0 = skn[col], k1 = skn[col + 1];
                float qk, d, s;
                qk = sS[mi][ni][0]; d = sq[mi][0] + k0 - 2.0f * qk + YAT_EPS;
                s = fminf(scale * __fdividef(qk * qk, d), 75.0f);
                sS[mi][ni][0] = __expf(s); l[mi][0] += sS[mi][ni][0];
                qk = sS[mi][ni][1]; d = sq[mi][0] + k1 - 2.0f * qk + YAT_EPS;
                s = fminf(scale * __fdividef(qk * qk, d), 75.0f);
                sS[mi][ni][1] = __expf(s); l[mi][0] += sS[mi][ni][1];
                qk = sS[mi][ni][2]; d = sq[mi][1] + k0 - 2.0f * qk + YAT_EPS;
                s = fminf(scale * __fdividef(qk * qk, d), 75.0f);
                sS[mi][ni][2] = __expf(s); l[mi][1] += sS[mi][ni][2];
                qk = sS[mi][ni][3]; d = sq[mi][1] + k1 - 2.0f * qk + YAT_EPS;
                s = fminf(scale * __fdividef(qk * qk, d), 75.0f);
                sS[mi][ni][3] = __expf(s); l[mi][1] += sS[mi][ni][3];
            }
        }

#pragma unroll
        for (int kk = 0; kk < 4; kk++) {
            uint32_t ph[2][4], pl[2][4];
#pragma unroll
            for (int mi = 0; mi < 2; mi++) {
                const float* e = sS[mi][2 * kk];
                const float* f = sS[mi][2 * kk + 1];
                uint32_t u0, u1;
                float h0, h1;
                u0 = __float_as_uint(e[0]); u1 = __float_as_uint(e[1]);
                ph[mi][0] = prmt7632(u0, u1);
                h0 = __uint_as_float(u0 & 0xffff0000u); h1 = __uint_as_float(u1 & 0xffff0000u);
                pl[mi][0] = pkbf16x2(e[0] - h0, e[1] - h1);
                u0 = __float_as_uint(e[2]); u1 = __float_as_uint(e[3]);
                ph[mi][1] = prmt7632(u0, u1);
                h0 = __uint_as_float(u0 & 0xffff0000u); h1 = __uint_as_float(u1 & 0xffff0000u);
                pl[mi][1] = pkbf16x2(e[2] - h0, e[3] - h1);
                u0 = __float_as_uint(f[0]); u1 = __float_as_uint(f[1]);
                ph[mi][2] = prmt7632(u0, u1);
                h0 = __uint_as_float(u0 & 0xffff0000u); h1 = __uint_as_float(u1 & 0xffff0000u);
                pl[mi][2] = pkbf16x2(f[0] - h0, f[1] - h1);
                u0 = __float_as_uint(f[2]); u1 = __float_as_uint(f[3]);
                ph[mi][3] = prmt7632(u0, u1);
                h0 = __uint_as_float(u0 & 0xffff0000u); h1 = __uint_as_float(u1 & 0xffff0000u);
                pl[mi][3] = pkbf16x2(f[2] - h0, f[3] - h1);
            }
#pragma unroll
            for (int db = 0; db < 4; db++) {
                const uint32_t voff = ((kk * 16 + (lane & 15)) * LDS + db * 16 + (lane >> 4) * 8) * 2;
                uint32_t th[4], tl[4];
                ldsm_x4_t(th, uVh + voff);
                ldsm_x4_t(tl, uVl + voff);
#pragma unroll
                for (int mi = 0; mi < 2; mi++) {
                    mma_bf16(accO[mi][2 * db],     ph[mi], th);
                    mma_bf16(accO[mi][2 * db + 1], ph[mi], th + 2);
                    mma_bf16(accO[mi][2 * db],     ph[mi], tl);
                    mma_bf16(accO[mi][2 * db + 1], ph[mi], tl + 2);
                    mma_bf16(accO[mi][2 * db],     pl[mi], th);
                    mma_bf16(accO[mi][2 * db + 1], pl[mi], th + 2);
                }
            }
        }
    }

#pragma unroll
    for (int off = 1; off <= 2; off <<= 1) {
#pragma unroll
        for (int mi = 0; mi < 2; mi++) {
            l[mi][0] += __shfl_xor_sync(0xffffffffu, l[mi][0], off);
            l[mi][1] += __shfl_xor_sync(0xffffffffu, l[mi][1], off);
        }
    }

#pragma unroll
    for (int mi = 0; mi < 2; mi++) {
        float inv0 = __fdividef(1.0f, l[mi][0]), inv1 = __fdividef(1.0f, l[mi][1]);
        size_t ro = (tokq + w * 32 + mi * 16 + g) * CE + h * CD;
#pragma unroll
        for (int ni = 0; ni < 8; ni++) {
            int c = ni * 8 + tg * 2;
            float o00 = accO[mi][ni][0] * inv0, o01 = accO[mi][ni][1] * inv0;
            float o10 = accO[mi][ni][2] * inv1, o11 = accO[mi][ni][3] * inv1;
            __nv_bfloat16 h00 = __float2bfloat16(o00), h01 = __float2bfloat16(o01);
            __nv_bfloat16 h10 = __float2bfloat16(o10), h11 = __float2bfloat16(o11);
            *(__nv_bfloat162*)&Ohm[ro + c] = __nv_bfloat162(h00, h01);
            *(__nv_bfloat162*)&Ohm[ro + 8 * CE + c] = __nv_bfloat162(h10, h11);
            *(__nv_bfloat162*)&Olm[ro + c] = __nv_bfloat162(
                __float2bfloat16(o00 - __bfloat162float(h00)),
                __float2bfloat16(o01 - __bfloat162float(h01)));
            *(__nv_bfloat162*)&Olm[ro + 8 * CE + c] = __nv_bfloat162(
                __float2bfloat16(o10 - __bfloat162float(h10)),
                __float2bfloat16(o11 - __bfloat162float(h11)));
        }
    }
}

// ---------------------------------------------------------------------------
extern "C" void kernel_launch(void* const* d_in, const int* in_sizes, int n_in,
                              void* d_out, int out_size)
{
    (void)in_sizes; (void)n_in; (void)out_size;
    const float* query = (const float*)d_in[0];
    const float* Wq    = (const float*)d_in[1];
    const float* bq    = (const float*)d_in[2];
    const float* Wk    = (const float*)d_in[3];
    const float* bk    = (const float*)d_in[4];
    const float* Wv    = (const float*)d_in[5];
    const float* bv    = (const float*)d_in[6];
    const float* Wo    = (const float*)d_in[7];
    const float* bo    = (const float*)d_in[8];
    const float* alpha = (const float*)d_in[9];

    float *qn, *kn;
    cudaGetSymbolAddress((void**)&qn, g_qn);
    cudaGetSymbolAddress((void**)&kn, g_kn);
    __nv_bfloat16 *xh, *xl, *oh, *ol, *wqh, *wql, *wkh, *wkl, *wvh, *wvl, *woh, *wol;
    __nv_bfloat16 *aqh, *aql, *akh, *akl, *avh, *avl;
    cudaGetSymbolAddress((void**)&xh, g_xh);   cudaGetSymbolAddress((void**)&xl, g_xl);
    cudaGetSymbolAddress((void**)&oh, g_oh);   cudaGetSymbolAddress((void**)&ol, g_ol);
    cudaGetSymbolAddress((void**)&wqh, g_wqh); cudaGetSymbolAddress((void**)&wql, g_wql);
    cudaGetSymbolAddress((void**)&wkh, g_wkh); cudaGetSymbolAddress((void**)&wkl, g_wkl);
    cudaGetSymbolAddress((void**)&wvh, g_wvh); cudaGetSymbolAddress((void**)&wvl, g_wvl);
    cudaGetSymbolAddress((void**)&woh, g_woh); cudaGetSymbolAddress((void**)&wol, g_wol);
    cudaGetSymbolAddress((void**)&aqh, g_aqh); cudaGetSymbolAddress((void**)&aql, g_aql);
    cudaGetSymbolAddress((void**)&akh, g_akh); cudaGetSymbolAddress((void**)&akl, g_akl);
    cudaGetSymbolAddress((void**)&avh, g_avh); cudaGetSymbolAddress((void**)&avl, g_avl);

    const int nx4 = CM * CE / 4;
    const int nw4 = CE * CE / 4;
    {
        SplitJob jx = {query, xh, xl};
        split_bf16_multi<<<dim3(nx4 / 256, 1), 256>>>(jx, jx, jx, jx, nx4);
        SplitJob jq = {Wq, wqh, wql}, jk = {Wk, wkh, wkl}, jv = {Wv, wvh, wvl}, jo = {Wo, woh, wol};
        split_bf16_multi<<<dim3(nw4 / 256, 4), 256>>>(jq, jk, jv, jo, nw4);
    }

    cudaFuncSetAttribute(hgemm_nt_3split, cudaFuncAttributeMaxDynamicSharedMemorySize, HG_SMEM);
    {
        GemmJob jq = {xh, xl, wqh, wql, bq, nullptr, aqh, aql, qn};
        GemmJob jk = {xh, xl, wkh, wkl, bk, nullptr, akh, akl, kn};
        GemmJob jv = {xh, xl, wvh, wvl, bv, nullptr, avh, avl, nullptr};
        hgemm_nt_3split<<<dim3(CE / 256, CM / 128, 3), 256, HG_SMEM>>>(jq, jk, jv, CM, CE, CE);
    }

    cudaFuncSetAttribute(yat_attn_mma, cudaFuncAttributeMaxDynamicSharedMemorySize, ATTN_SMEM);
    yat_attn_mma<<<dim3(CS / 256, CH, CB), 256, ATTN_SMEM>>>(
        aqh, aql, akh, akl, avh, avl, qn, kn, oh, ol, alpha);

    {
        GemmJob jo = {oh, ol, woh, wol, bo, (float*)d_out, nullptr, nullptr, nullptr};
        hgemm_nt_3split<<<dim3(CE / 256, CM / 128, 1), 256, HG_SMEM>>>(jo, jo, jo, CM, CE, CE);
    }
}

// round 14
// speedup vs baseline: 1.0061x; 1.0061x over previous
#include <cuda_runtime.h>
#include <cuda_bf16.h>
#include <math.h>
#include <stdint.h>

#define CB 2
#define CS 2048
#define CE 1024
#define CH 16
#define CD 64
#define CM (CB*CS)          // 4096 tokens
#define YAT_EPS 1e-5f

__device__ __forceinline__ uint32_t smem_u32(const void* p) {
    uint32_t a;
    asm("{ .reg .u64 t; cvta.to.shared.u64 t, %1; cvt.u32.u64 %0, t; }" : "=r"(a) : "l"(p));
    return a;
}

// ---- mma.sync / ldmatrix / cp.async helpers (portable to non-'a' sm_103) ----
__device__ __forceinline__ void ldsm_x4(uint32_t* r, uint32_t addr) {
    asm volatile("ldmatrix.sync.aligned.m8n8.x4.shared.b16 {%0,%1,%2,%3}, [%4];"
        : "=r"(r[0]), "=r"(r[1]), "=r"(r[2]), "=r"(r[3]) : "r"(addr));
}
__device__ __forceinline__ void ldsm_x4_t(uint32_t* r, uint32_t addr) {
    asm volatile("ldmatrix.sync.aligned.m8n8.x4.trans.shared.b16 {%0,%1,%2,%3}, [%4];"
        : "=r"(r[0]), "=r"(r[1]), "=r"(r[2]), "=r"(r[3]) : "r"(addr));
}
__device__ __forceinline__ void mma_bf16(float* c, const uint32_t* a, const uint32_t* b) {
    asm volatile(
        "mma.sync.aligned.m16n8k16.row.col.f32.bf16.bf16.f32 "
        "{%0,%1,%2,%3}, {%4,%5,%6,%7}, {%8,%9}, {%0,%1,%2,%3};"
        : "+f"(c[0]), "+f"(c[1]), "+f"(c[2]), "+f"(c[3])
        : "r"(a[0]), "r"(a[1]), "r"(a[2]), "r"(a[3]), "r"(b[0]), "r"(b[1]));
}
__device__ __forceinline__ uint32_t prmt7632(uint32_t a, uint32_t b) {
    uint32_t r; asm("prmt.b32 %0, %1, %2, 0x7632;" : "=r"(r) : "r"(a), "r"(b)); return r;
}
__device__ __forceinline__ uint32_t pkbf16x2(float lo, float hi) {
    uint32_t r; asm("cvt.rn.bf16x2.f32 %0, %1, %2;" : "=r"(r) : "f"(hi), "f"(lo)); return r;
}
__device__ __forceinline__ void cpasync16(uint32_t dst, const void* src) {
    asm volatile("cp.async.cg.shared.global [%0], [%1], 16;" :: "r"(dst), "l"(src));
}
#define CP_COMMIT() asm volatile("cp.async.commit_group;" ::: "memory")
#define CP_WAIT(n)  asm volatile("cp.async.wait_group %0;" :: "n"(n) : "memory")

// FMA-pipe reciprocal: bit-hack seed + 2 Newton iterations (no MUFU).
// d is always positive and O(100) here; after 2 NR the error is ~1 ulp-ish.
__device__ __forceinline__ float rcp_fma(float d) {
    float r = __uint_as_float(0x7EF311C3u - __float_as_uint(d));
    r = r * __fmaf_rn(-d, r, 2.0f);
    r = r * __fmaf_rn(-d, r, 2.0f);
    return r;
}

// ---- Scratch (__device__ globals; allocation-free rule) ----
__device__ __nv_bfloat16 g_xh[(size_t)CM*CE], g_xl[(size_t)CM*CE];
__device__ __nv_bfloat16 g_oh[(size_t)CM*CE], g_ol[(size_t)CM*CE];
__device__ __nv_bfloat16 g_wqh[(size_t)CE*CE], g_wql[(size_t)CE*CE];
__device__ __nv_bfloat16 g_wkh[(size_t)CE*CE], g_wkl[(size_t)CE*CE];
__device__ __nv_bfloat16 g_wvh[(size_t)CE*CE], g_wvl[(size_t)CE*CE];
__device__ __nv_bfloat16 g_woh[(size_t)CE*CE], g_wol[(size_t)CE*CE];
__device__ __nv_bfloat16 g_aqh[(size_t)CM*CE], g_aql[(size_t)CM*CE];
__device__ __nv_bfloat16 g_akh[(size_t)CM*CE], g_akl[(size_t)CM*CE];
__device__ __nv_bfloat16 g_avh[(size_t)CM*CE], g_avl[(size_t)CM*CE];
__device__ float g_qn[(size_t)CH*CM];
__device__ float g_kn[(size_t)CH*CM];

// ---------------------------------------------------------------------------
__global__ __launch_bounds__(256) void zero_norms(float* qn, float* kn)
{
    int i = blockIdx.x * blockDim.x + threadIdx.x;
    qn[i] = 0.0f; kn[i] = 0.0f;
}

// ---------------------------------------------------------------------------
struct SplitJob { const float* x; __nv_bfloat16* hi; __nv_bfloat16* lo; };

__global__ __launch_bounds__(256) void split_bf16_multi(
    SplitJob j0, SplitJob j1, SplitJob j2, SplitJob j3, int n4)
{
    int i = blockIdx.x * blockDim.x + threadIdx.x;
    if (i >= n4) return;
    SplitJob j = (blockIdx.y == 0) ? j0 : (blockIdx.y == 1) ? j1 : (blockIdx.y == 2) ? j2 : j3;
    float4 v = ((const float4*)j.x)[i];
    union { __nv_bfloat16 b[4]; uint2 u; } H, L;
    float a[4] = {v.x, v.y, v.z, v.w};
#pragma unroll
    for (int jj = 0; jj < 4; jj++) {
        __nv_bfloat16 h = __float2bfloat16(a[jj]);
        H.b[jj] = h;
        L.b[jj] = __float2bfloat16(a[jj] - __bfloat162float(h));
    }
    ((uint2*)j.hi)[i] = H.u;
    ((uint2*)j.lo)[i] = L.u;
}

// ---------------------------------------------------------------------------
// C = A @ B^T + bias via mma.sync bf16 3-split (R12 proven config).
// ---------------------------------------------------------------------------
#define LDA 40
#define STB (128*LDA*2)
#define HG_SMEM (2*4*STB)

struct GemmJob {
    const __nv_bfloat16 *Ah, *Al, *Bh, *Bl;
    const float* bias;
    float* C;
    __nv_bfloat16 *Chi, *Clo;
    float* norm;
};

__global__ __launch_bounds__(256) void hgemm_nt_3split(
    GemmJob j0, GemmJob j1, GemmJob j2, int M, int N, int K)
{
    extern __shared__ __nv_bfloat16 smem[];
    const uint32_t uS = smem_u32(smem);
    const GemmJob jb = (blockIdx.z == 0) ? j0 : (blockIdx.z == 1) ? j1 : j2;

    const int tid = threadIdx.x, lane = tid & 31, wid = tid >> 5;
    const int wm = wid >> 2, wn = wid & 3;
    const int row0 = blockIdx.y * 128, col0 = blockIdx.x * 128;

    float acc[4][4][4];
#pragma unroll
    for (int i = 0; i < 4; i++)
#pragma unroll
        for (int j = 0; j < 4; j++)
#pragma unroll
            for (int f = 0; f < 4; f++) acc[i][j][f] = 0.0f;

    const int a_row = lane & 15, a_kg = lane >> 4;
    const int b_row = ((lane >> 4) & 1) * 8 + (lane & 7);
    const int b_kg  = (lane >> 3) & 1;

    const int gr = tid >> 2;
    const int gc = (tid & 3) * 8;

    const int NT = K / 32;

    auto load_st = [&](int s, int t) {
        const int k0 = t * 32;
        const uint32_t sbase = uS + s * 4 * STB;
#pragma unroll
        for (int pp = 0; pp < 2; pp++) {
            int r = pp * 64 + gr;
            uint32_t doff = (uint32_t)(r * LDA + gc) * 2;
            size_t ga = (size_t)(row0 + r) * K + k0 + gc;
            size_t gb = (size_t)(col0 + r) * K + k0 + gc;
            cpasync16(sbase + 0 * STB + doff, &jb.Ah[ga]);
            cpasync16(sbase + 1 * STB + doff, &jb.Al[ga]);
            cpasync16(sbase + 2 * STB + doff, &jb.Bh[gb]);
            cpasync16(sbase + 3 * STB + doff, &jb.Bl[gb]);
        }
    };

    load_st(0, 0);
    CP_COMMIT();

    for (int t = 0; t < NT; t++) {
        CP_WAIT(0);
        __syncthreads();
        if (t + 1 < NT) {
            load_st((t + 1) & 1, t + 1);
            CP_COMMIT();
        }

        const uint32_t sA_h = uS + ((t & 1) * 4 + 0) * STB;
        const uint32_t sA_l = uS + ((t & 1) * 4 + 1) * STB;
        const uint32_t sB_h = uS + ((t & 1) * 4 + 2) * STB;
        const uint32_t sB_l = uS + ((t & 1) * 4 + 3) * STB;

#pragma unroll
        for (int kk = 0; kk < 2; kk++) {
            const uint32_t aoff = ((wm * 64 + a_row) * LDA + kk * 16 + a_kg * 8) * 2;
            const uint32_t boff0 = ((wn * 32 + b_row) * LDA + kk * 16 + b_kg * 8) * 2;
            const uint32_t boff1 = boff0 + 16 * LDA * 2;

            uint32_t bh_f[4][2], bl_f[4][2], af[4][4];
            {
                uint32_t tt[4];
                ldsm_x4(tt, sB_h + boff0);
                bh_f[0][0] = tt[0]; bh_f[0][1] = tt[1]; bh_f[1][0] = tt[2]; bh_f[1][1] = tt[3];
                ldsm_x4(tt, sB_h + boff1);
                bh_f[2][0] = tt[0]; bh_f[2][1] = tt[1]; bh_f[3][0] = tt[2]; bh_f[3][1] = tt[3];
                ldsm_x4(tt, sB_l + boff0);
                bl_f[0][0] = tt[0]; bl_f[0][1] = tt[1]; bl_f[1][0] = tt[2]; bl_f[1][1] = tt[3];
                ldsm_x4(tt, sB_l + boff1);
                bl_f[2][0] = tt[0]; bl_f[2][1] = tt[1]; bl_f[3][0] = tt[2]; bl_f[3][1] = tt[3];
            }
#pragma unroll
            for (int mi = 0; mi < 4; mi++)
                ldsm_x4(af[mi], sA_h + aoff + mi * 16 * LDA * 2);
#pragma unroll
            for (int mi = 0; mi < 4; mi++)
#pragma unroll
                for (int ni = 0; ni < 4; ni++)
                    mma_bf16(acc[mi][ni], af[mi], bh_f[ni]);
#pragma unroll
            for (int mi = 0; mi < 4; mi++)
#pragma unroll
                for (int ni = 0; ni < 4; ni++)
                    mma_bf16(acc[mi][ni], af[mi], bl_f[ni]);
#pragma unroll
            for (int mi = 0; mi < 4; mi++)
                ldsm_x4(af[mi], sA_l + aoff + mi * 16 * LDA * 2);
#pragma unroll
            for (int mi = 0; mi < 4; mi++)
#pragma unroll
                for (int ni = 0; ni < 4; ni++)
                    mma_bf16(acc[mi][ni], af[mi], bh_f[ni]);
        }
    }
    __syncthreads();

    const int erow = lane >> 2, ecol = (lane & 3) * 2;
    const int hh = (col0 + wn * 32) >> 6;
#pragma unroll
    for (int mi = 0; mi < 4; mi++) {
        float s0 = 0.0f, s1 = 0.0f;
#pragma unroll
        for (int ni = 0; ni < 4; ni++) {
            int rg = row0 + wm * 64 + mi * 16 + erow;
            int cg = col0 + wn * 32 + ni * 8 + ecol;
            float2 bb = *(const float2*)&jb.bias[cg];
            float o00 = acc[mi][ni][0] + bb.x, o01 = acc[mi][ni][1] + bb.y;
            float o10 = acc[mi][ni][2] + bb.x, o11 = acc[mi][ni][3] + bb.y;
            s0 += o00 * o00 + o01 * o01;
            s1 += o10 * o10 + o11 * o11;
            size_t i0 = (size_t)rg * N + cg, i1 = (size_t)(rg + 8) * N + cg;
            if (jb.C) {
                *(float2*)&jb.C[i0] = make_float2(o00, o01);
                *(float2*)&jb.C[i1] = make_float2(o10, o11);
            }
            if (jb.Chi) {
                __nv_bfloat16 h00 = __float2bfloat16(o00), h01 = __float2bfloat16(o01);
                __nv_bfloat16 h10 = __float2bfloat16(o10), h11 = __float2bfloat16(o11);
                *(__nv_bfloat162*)&jb.Chi[i0] = __nv_bfloat162(h00, h01);
                *(__nv_bfloat162*)&jb.Chi[i1] = __nv_bfloat162(h10, h11);
                *(__nv_bfloat162*)&jb.Clo[i0] = __nv_bfloat162(
                    __float2bfloat16(o00 - __bfloat162float(h00)),
                    __float2bfloat16(o01 - __bfloat162float(h01)));
                *(__nv_bfloat162*)&jb.Clo[i1] = __nv_bfloat162(
                    __float2bfloat16(o10 - __bfloat162float(h10)),
                    __float2bfloat16(o11 - __bfloat162float(h11)));
            }
        }
        if (jb.norm) {
            int rg = row0 + wm * 64 + mi * 16 + erow;
            atomicAdd(&jb.norm[(size_t)hh * CM + rg], s0);
            atomicAdd(&jb.norm[(size_t)hh * CM + rg + 8], s1);
        }
    }
}

// ---------------------------------------------------------------------------
// YAT flash attention: 256 q-rows/CTA, 32 q-rows/warp; FMA-pipe reciprocal
// (MUFU now carries only EX2).
// ---------------------------------------------------------------------------
#define LDS 72
#define AQ_EL 18432
#define KV_EL 18432
#define ATTN_SMEM ((2*AQ_EL + 2*KV_EL)*2 + 512 + 128)   // 148096 B

__global__ void __launch_bounds__(256, 1) yat_attn_mma(
    const __nv_bfloat16* __restrict__ Qhm, const __nv_bfloat16* __restrict__ Qlm,
    const __nv_bfloat16* __restrict__ Khm, const __nv_bfloat16* __restrict__ Klm,
    const __nv_bfloat16* __restrict__ Vhm, const __nv_bfloat16* __restrict__ Vlm,
    const float* __restrict__ qn, const float* __restrict__ kn,
    __nv_bfloat16* __restrict__ Ohm, __nv_bfloat16* __restrict__ Olm,
    const float* __restrict__ alphap)
{
    extern __shared__ __nv_bfloat16 sb[];
    const uint32_t uS = smem_u32(sb);
    const uint32_t uQh = uS, uQl = uS + AQ_EL * 2;
    const uint32_t uKV = uS + 2 * AQ_EL * 2;
    const uint32_t uKN = uS + (2 * AQ_EL + 2 * KV_EL) * 2;

    const int tid = threadIdx.x, lane = tid & 31, w = tid >> 5;
    const int g = lane >> 2, tg = lane & 3;
    const int b = blockIdx.z, h = blockIdx.y;
    const int q0 = blockIdx.x * 256;
    const size_t tokq = (size_t)b * CS + q0;

    const float scale = powf(8.0f / logf(65.0f), alphap[0]);

    {
        int c8 = tid & 7;
        int rb = tid >> 3;
#pragma unroll
        for (int i = 0; i < 8; i++) {
            int r = rb + i * 32;
            size_t gq = (tokq + r) * CE + h * CD + c8 * 8;
            *(uint4*)&sb[r * LDS + c8 * 8] = *(const uint4*)&Qhm[gq];
            *(uint4*)&sb[AQ_EL + r * LDS + c8 * 8] = *(const uint4*)&Qlm[gq];
        }
    }

    float sq[2][2];
#pragma unroll
    for (int mi = 0; mi < 2; mi++) {
        sq[mi][0] = qn[(size_t)h * CM + tokq + w * 32 + mi * 16 + g];
        sq[mi][1] = qn[(size_t)h * CM + tokq + w * 32 + mi * 16 + g + 8];
    }

    float l[2][2] = {{0.f, 0.f}, {0.f, 0.f}};
    float accO[2][8][4];
#pragma unroll
    for (int mi = 0; mi < 2; mi++)
#pragma unroll
        for (int i = 0; i < 8; i++)
#pragma unroll
            for (int j = 0; j < 4; j++) accO[mi][i][j] = 0.0f;

    const int a_row = lane & 15, a_kg = lane >> 4;
    const int b_row = ((lane >> 4) & 1) * 8 + (lane & 7);
    const int b_kg  = (lane >> 3) & 1;

    auto load_kv = [&](int stg, int t) {
        int r = tid >> 2, c2 = (tid & 3) * 2;
        size_t gk = ((size_t)b * CS + t * 64 + r) * CE + h * CD;
        const uint32_t sbase = uKV + (uint32_t)stg * KV_EL * 2u;
#pragma unroll
        for (int u = 0; u < 2; u++) {
            int cc = (c2 + u) * 8;
            uint32_t doff = (uint32_t)(r * LDS + cc) * 2;
            cpasync16(sbase + 0u * 9216u + doff, &Khm[gk + cc]);
            cpasync16(sbase + 1u * 9216u + doff, &Klm[gk + cc]);
            cpasync16(sbase + 2u * 9216u + doff, &Vhm[gk + cc]);
            cpasync16(sbase + 3u * 9216u + doff, &Vlm[gk + cc]);
        }
        if (tid < 16)
            cpasync16(uKN + (uint32_t)stg * 256u + tid * 16,
                      &kn[(size_t)h * CM + b * CS + t * 64 + tid * 4]);
    };

    load_kv(0, 0);
    CP_COMMIT();

    const int NT = CS / 64;
    for (int t = 0; t < NT; t++) {
        CP_WAIT(0);
        __syncthreads();
        if (t + 1 < NT) {
            load_kv((t + 1) & 1, t + 1);
            CP_COMMIT();
        }
        const uint32_t kb = uKV + (uint32_t)(t & 1) * KV_EL * 2u;
        const uint32_t uKh = kb, uKl = kb + 9216u, uVh = kb + 18432u, uVl = kb + 27648u;
        const float* skn = (const float*)((const char*)sb + (2 * AQ_EL + 2 * KV_EL) * 2 + (t & 1) * 256);

        float sS[2][8][4];
#pragma unroll
        for (int mi = 0; mi < 2; mi++)
#pragma unroll
            for (int i = 0; i < 8; i++)
#pragma unroll
                for (int j = 0; j < 4; j++) sS[mi][i][j] = 0.0f;

#pragma unroll
        for (int kk = 0; kk < 4; kk++) {
            uint32_t ah[2][4], al[2][4];
#pragma unroll
            for (int mi = 0; mi < 2; mi++) {
                const uint32_t aoff = ((w * 32 + mi * 16 + a_row) * LDS + kk * 16 + a_kg * 8) * 2;
                ldsm_x4(ah[mi], uQh + aoff);
                ldsm_x4(al[mi], uQl + aoff);
            }
#pragma unroll
            for (int nb = 0; nb < 4; nb++) {
                const uint32_t boff = ((nb * 16 + b_row) * LDS + kk * 16 + b_kg * 8) * 2;
                uint32_t th[4], tl[4];
                ldsm_x4(th, uKh + boff);
                ldsm_x4(tl, uKl + boff);
#pragma unroll
                for (int mi = 0; mi < 2; mi++) {
                    mma_bf16(sS[mi][2 * nb],     ah[mi], th);
                    mma_bf16(sS[mi][2 * nb + 1], ah[mi], th + 2);
                    mma_bf16(sS[mi][2 * nb],     ah[mi], tl);
                    mma_bf16(sS[mi][2 * nb + 1], ah[mi], tl + 2);
                    mma_bf16(sS[mi][2 * nb],     al[mi], th);
                    mma_bf16(sS[mi][2 * nb + 1], al[mi], th + 2);
                }
            }
        }

        // YAT score -> exp; reciprocal on FMA pipe (MUFU carries only EX2)
#pragma unroll
        for (int mi = 0; mi < 2; mi++) {
#pragma unroll
            for (int ni = 0; ni < 8; ni++) {
                int col = ni * 8 + tg * 2;
                float k0 = skn[col], k1 = skn[col + 1];
                float qk, d, s;
                qk = sS[mi][ni][0]; d = sq[mi][0] + k0 - 2.0f * qk + YAT_EPS;
                s = fminf(scale * (qk * qk) * rcp_fma(d), 75.0f);
                sS[mi][ni][0] = __expf(s); l[mi][0] += sS[mi][ni][0];
                qk = sS[mi][ni][1]; d = sq[mi][0] + k1 - 2.0f * qk + YAT_EPS;
                s = fminf(scale * (qk * qk) * rcp_fma(d), 75.0f);
                sS[mi][ni][1] = __expf(s); l[mi][0] += sS[mi][ni][1];
                qk = sS[mi][ni][2]; d = sq[mi][1] + k0 - 2.0f * qk + YAT_EPS;
                s = fminf(scale * (qk * qk) * rcp_fma(d), 75.0f);
                sS[mi][ni][2] = __expf(s); l[mi][1] += sS[mi][ni][2];
                qk = sS[mi][ni][3]; d = sq[mi][1] + k1 - 2.0f * qk + YAT_EPS;
                s = fminf(scale * (qk * qk) * rcp_fma(d), 75.0f);
                sS[mi][ni][3] = __expf(s); l[mi][1] += sS[mi][ni][3];
            }
        }

#pragma unroll
        for (int kk = 0; kk < 4; kk++) {
            uint32_t ph[2][4], pl[2][4];
#pragma unroll
            for (int mi = 0; mi < 2; mi++) {
                const float* e = sS[mi][2 * kk];
                const float* f = sS[mi][2 * kk + 1];
                uint32_t u0, u1;
                float h0, h1;
                u0 = __float_as_uint(e[0]); u1 = __float_as_uint(e[1]);
                ph[mi][0] = prmt7632(u0, u1);
                h0 = __uint_as_float(u0 & 0xffff0000u); h1 = __uint_as_float(u1 & 0xffff0000u);
                pl[mi][0] = pkbf16x2(e[0] - h0, e[1] - h1);
                u0 = __float_as_uint(e[2]); u1 = __float_as_uint(e[3]);
                ph[mi][1] = prmt7632(u0, u1);
                h0 = __uint_as_float(u0 & 0xffff0000u); h1 = __uint_as_float(u1 & 0xffff0000u);
                pl[mi][1] = pkbf16x2(e[2] - h0, e[3] - h1);
                u0 = __float_as_uint(f[0]); u1 = __float_as_uint(f[1]);
                ph[mi][2] = prmt7632(u0, u1);
                h0 = __uint_as_float(u0 & 0xffff0000u); h1 = __uint_as_float(u1 & 0xffff0000u);
                pl[mi][2] = pkbf16x2(f[0] - h0, f[1] - h1);
                u0 = __float_as_uint(f[2]); u1 = __float_as_uint(f[3]);
                ph[mi][3] = prmt7632(u0, u1);
                h0 = __uint_as_float(u0 & 0xffff0000u); h1 = __uint_as_float(u1 & 0xffff0000u);
                pl[mi][3] = pkbf16x2(f[2] - h0, f[3] - h1);
            }
#pragma unroll
            for (int db = 0; db < 4; db++) {
                const uint32_t voff = ((kk * 16 + (lane & 15)) * LDS + db * 16 + (lane >> 4) * 8) * 2;
                uint32_t th[4], tl[4];
                ldsm_x4_t(th, uVh + voff);
                ldsm_x4_t(tl, uVl + voff);
#pragma unroll
                for (int mi = 0; mi < 2; mi++) {
                    mma_bf16(accO[mi][2 * db],     ph[mi], th);
                    mma_bf16(accO[mi][2 * db + 1], ph[mi], th + 2);
                    mma_bf16(accO[mi][2 * db],     ph[mi], tl);
                    mma_bf16(accO[mi][2 * db + 1], ph[mi], tl + 2);
                    mma_bf16(accO[mi][2 * db],     pl[mi], th);
                    mma_bf16(accO[mi][2 * db + 1], pl[mi], th + 2);
                }
            }
        }
    }

#pragma unroll
    for (int off = 1; off <= 2; off <<= 1) {
#pragma unroll
        for (int mi = 0; mi < 2; mi++) {
            l[mi][0] += __shfl_xor_sync(0xffffffffu, l[mi][0], off);
            l[mi][1] += __shfl_xor_sync(0xffffffffu, l[mi][1], off);
        }
    }

#pragma unroll
    for (int mi = 0; mi < 2; mi++) {
        float inv0 = __fdividef(1.0f, l[mi][0]), inv1 = __fdividef(1.0f, l[mi][1]);
        size_t ro = (tokq + w * 32 + mi * 16 + g) * CE + h * CD;
#pragma unroll
        for (int ni = 0; ni < 8; ni++) {
            int c = ni * 8 + tg * 2;
            float o00 = accO[mi][ni][0] * inv0, o01 = accO[mi][ni][1] * inv0;
            float o10 = accO[mi][ni][2] * inv1, o11 = accO[mi][ni][3] * inv1;
            __nv_bfloat16 h00 = __float2bfloat16(o00), h01 = __float2bfloat16(o01);
            __nv_bfloat16 h10 = __float2bfloat16(o10), h11 = __float2bfloat16(o11);
            *(__nv_bfloat162*)&Ohm[ro + c] = __nv_bfloat162(h00, h01);
            *(__nv_bfloat162*)&Ohm[ro + 8 * CE + c] = __nv_bfloat162(h10, h11);
            *(__nv_bfloat162*)&Olm[ro + c] = __nv_bfloat162(
                __float2bfloat16(o00 - __bfloat162float(h00)),
                __float2bfloat16(o01 - __bfloat162float(h01)));
            *(__nv_bfloat162*)&Olm[ro + 8 * CE + c] = __nv_bfloat162(
                __float2bfloat16(o10 - __bfloat162float(h10)),
                __float2bfloat16(o11 - __bfloat162float(h11)));
        }
    }
}

// ---------------------------------------------------------------------------
extern "C" void kernel_launch(void* const* d_in, const int* in_sizes, int n_in,
                              void* d_out, int out_size)
{
    (void)in_sizes; (void)n_in; (void)out_size;
    const float* query = (const float*)d_in[0];
    const float* Wq    = (const float*)d_in[1];
    const float* bq    = (const float*)d_in[2];
    const float* Wk    = (const float*)d_in[3];
    const float* bk    = (const float*)d_in[4];
    const float* Wv    = (const float*)d_in[5];
    const float* bv    = (const float*)d_in[6];
    const float* Wo    = (const float*)d_in[7];
    const float* bo    = (const float*)d_in[8];
    const float* alpha = (const float*)d_in[9];

    float *qn, *kn;
    cudaGetSymbolAddress((void**)&qn, g_qn);
    cudaGetSymbolAddress((void**)&kn, g_kn);
    __nv_bfloat16 *xh, *xl, *oh, *ol, *wqh, *wql, *wkh, *wkl, *wvh, *wvl, *woh, *wol;
    __nv_bfloat16 *aqh, *aql, *akh, *akl, *avh, *avl;
    cudaGetSymbolAddress((void**)&xh, g_xh);   cudaGetSymbolAddress((void**)&xl, g_xl);
    cudaGetSymbolAddress((void**)&oh, g_oh);   cudaGetSymbolAddress((void**)&ol, g_ol);
    cudaGetSymbolAddress((void**)&wqh, g_wqh); cudaGetSymbolAddress((void**)&wql, g_wql);
    cudaGetSymbolAddress((void**)&wkh, g_wkh); cudaGetSymbolAddress((void**)&wkl, g_wkl);
    cudaGetSymbolAddress((void**)&wvh, g_wvh); cudaGetSymbolAddress((void**)&wvl, g_wvl);
    cudaGetSymbolAddress((void**)&woh, g_woh); cudaGetSymbolAddress((void**)&wol, g_wol);
    cudaGetSymbolAddress((void**)&aqh, g_aqh); cudaGetSymbolAddress((void**)&aql, g_aql);
    cudaGetSymbolAddress((void**)&akh, g_akh); cudaGetSymbolAddress((void**)&akl, g_akl);
    cudaGetSymbolAddress((void**)&avh, g_avh); cudaGetSymbolAddress((void**)&avl, g_avl);

    const int nx4 = CM * CE / 4;
    const int nw4 = CE * CE / 4;
    zero_norms<<<CH * CM / 256, 256>>>(qn, kn);
    {
        SplitJob jx = {query, xh, xl};
        split_bf16_multi<<<dim3(nx4 / 256, 1), 256>>>(jx, jx, jx, jx, nx4);
        SplitJob jq = {Wq, wqh, wql}, jk = {Wk, wkh, wkl}, jv = {Wv, wvh, wvl}, jo = {Wo, woh, wol};
        split_bf16_multi<<<dim3(nw4 / 256, 4), 256>>>(jq, jk, jv, jo, nw4);
    }

    cudaFuncSetAttribute(hgemm_nt_3split, cudaFuncAttributeMaxDynamicSharedMemorySize, HG_SMEM);
    {
        GemmJob jq = {xh, xl, wqh, wql, bq, nullptr, aqh, aql, qn};
        GemmJob jk = {xh, xl, wkh, wkl, bk, nullptr, akh, akl, kn};
        GemmJob jv = {xh, xl, wvh, wvl, bv, nullptr, avh, avl, nullptr};
        hgemm_nt_3split<<<dim3(CE / 128, CM / 128, 3), 256, HG_SMEM>>>(jq, jk, jv, CM, CE, CE);
    }

    cudaFuncSetAttribute(yat_attn_mma, cudaFuncAttributeMaxDynamicSharedMemorySize, ATTN_SMEM);
    yat_attn_mma<<<dim3(CS / 256, CH, CB), 256, ATTN_SMEM>>>(
        aqh, aql, akh, akl, avh, avl, qn, kn, oh, ol, alpha);

    {
        GemmJob jo = {oh, ol, woh, wol, bo, (float*)d_out, nullptr, nullptr, nullptr};
        hgemm_nt_3split<<<dim3(CE / 128, CM / 128, 1), 256, HG_SMEM>>>(jo, jo, jo, CM, CE, CE);
    }
}

// round 16
// speedup vs baseline: 1.0866x; 1.0800x over previous
#include <cuda_runtime.h>
#include <cuda_bf16.h>
#include <cuda_fp16.h>
#include <math.h>
#include <stdint.h>

#define CB 2
#define CS 2048
#define CE 1024
#define CH 16
#define CD 64
#define CM (CB*CS)          // 4096 tokens
#define YAT_EPS 1e-5f

__device__ __forceinline__ uint32_t smem_u32(const void* p) {
    uint32_t a;
    asm("{ .reg .u64 t; cvta.to.shared.u64 t, %1; cvt.u32.u64 %0, t; }" : "=r"(a) : "l"(p));
    return a;
}

// ---- mma.sync / ldmatrix / cp.async helpers (portable to non-'a' sm_103) ----
__device__ __forceinline__ void ldsm_x4(uint32_t* r, uint32_t addr) {
    asm volatile("ldmatrix.sync.aligned.m8n8.x4.shared.b16 {%0,%1,%2,%3}, [%4];"
        : "=r"(r[0]), "=r"(r[1]), "=r"(r[2]), "=r"(r[3]) : "r"(addr));
}
__device__ __forceinline__ void ldsm_x4_t(uint32_t* r, uint32_t addr) {
    asm volatile("ldmatrix.sync.aligned.m8n8.x4.trans.shared.b16 {%0,%1,%2,%3}, [%4];"
        : "=r"(r[0]), "=r"(r[1]), "=r"(r[2]), "=r"(r[3]) : "r"(addr));
}
__device__ __forceinline__ void mma_bf16(float* c, const uint32_t* a, const uint32_t* b) {
    asm volatile(
        "mma.sync.aligned.m16n8k16.row.col.f32.bf16.bf16.f32 "
        "{%0,%1,%2,%3}, {%4,%5,%6,%7}, {%8,%9}, {%0,%1,%2,%3};"
        : "+f"(c[0]), "+f"(c[1]), "+f"(c[2]), "+f"(c[3])
        : "r"(a[0]), "r"(a[1]), "r"(a[2]), "r"(a[3]), "r"(b[0]), "r"(b[1]));
}
__device__ __forceinline__ void mma_f16(float* c, const uint32_t* a, const uint32_t* b) {
    asm volatile(
        "mma.sync.aligned.m16n8k16.row.col.f32.f16.f16.f32 "
        "{%0,%1,%2,%3}, {%4,%5,%6,%7}, {%8,%9}, {%0,%1,%2,%3};"
        : "+f"(c[0]), "+f"(c[1]), "+f"(c[2]), "+f"(c[3])
        : "r"(a[0]), "r"(a[1]), "r"(a[2]), "r"(a[3]), "r"(b[0]), "r"(b[1]));
}
__device__ __forceinline__ uint32_t prmt7632(uint32_t a, uint32_t b) {
    uint32_t r; asm("prmt.b32 %0, %1, %2, 0x7632;" : "=r"(r) : "r"(a), "r"(b)); return r;
}
__device__ __forceinline__ uint32_t pkbf16x2(float lo, float hi) {
    uint32_t r; asm("cvt.rn.bf16x2.f32 %0, %1, %2;" : "=r"(r) : "f"(hi), "f"(lo)); return r;
}
__device__ __forceinline__ uint32_t pkf16x2(float lo, float hi) {
    uint32_t r; asm("cvt.rn.f16x2.f32 %0, %1, %2;" : "=r"(r) : "f"(hi), "f"(lo)); return r;
}
__device__ __forceinline__ void cpasync16(uint32_t dst, const void* src) {
    asm volatile("cp.async.cg.shared.global [%0], [%1], 16;" :: "r"(dst), "l"(src));
}
#define CP_COMMIT() asm volatile("cp.async.commit_group;" ::: "memory")
#define CP_WAIT(n)  asm volatile("cp.async.wait_group %0;" :: "n"(n) : "memory")

// FMA-pipe reciprocal (no MUFU): bit-hack seed + 2 Newton steps.
__device__ __forceinline__ float rcp_fma(float d) {
    float r = __uint_as_float(0x7EF311C3u - __float_as_uint(d));
    r = r * __fmaf_rn(-d, r, 2.0f);
    r = r * __fmaf_rn(-d, r, 2.0f);
    return r;
}

// ---- Scratch (__device__ globals; allocation-free rule) ----
__device__ __half g_xh[(size_t)CM*CE], g_xl[(size_t)CM*CE];
__device__ __half g_oh[(size_t)CM*CE];
__device__ __half g_wqh[(size_t)CE*CE], g_wql[(size_t)CE*CE];
__device__ __half g_wkh[(size_t)CE*CE], g_wkl[(size_t)CE*CE];
__device__ __half g_wvh[(size_t)CE*CE], g_wvl[(size_t)CE*CE];
__device__ __half g_woh[(size_t)CE*CE], g_wol[(size_t)CE*CE];
__device__ __half g_aqh[(size_t)CM*CE], g_aql[(size_t)CM*CE];
__device__ __half g_akh[(size_t)CM*CE], g_akl[(size_t)CM*CE];
__device__ __nv_bfloat16 g_avh[(size_t)CM*CE], g_avl[(size_t)CM*CE];
__device__ float g_qn[(size_t)CH*CM];
__device__ float g_kn[(size_t)CH*CM];

// ---------------------------------------------------------------------------
__global__ __launch_bounds__(256) void zero_norms(float* qn, float* kn)
{
    int i = blockIdx.x * blockDim.x + threadIdx.x;
    qn[i] = 0.0f; kn[i] = 0.0f;
}

// ---------------------------------------------------------------------------
struct SplitJob { const float* x; __half* hi; __half* lo; };

__global__ __launch_bounds__(256) void split_f16_multi(
    SplitJob j0, SplitJob j1, SplitJob j2, SplitJob j3, int n4)
{
    int i = blockIdx.x * blockDim.x + threadIdx.x;
    if (i >= n4) return;
    SplitJob j = (blockIdx.y == 0) ? j0 : (blockIdx.y == 1) ? j1 : (blockIdx.y == 2) ? j2 : j3;
    float4 v = ((const float4*)j.x)[i];
    union { __half b[4]; uint2 u; } H, L;
    float a[4] = {v.x, v.y, v.z, v.w};
#pragma unroll
    for (int jj = 0; jj < 4; jj++) {
        __half h = __float2half(a[jj]);
        H.b[jj] = h;
        L.b[jj] = __float2half(a[jj] - __half2float(h));
    }
    ((uint2*)j.hi)[i] = H.u;
    ((uint2*)j.lo)[i] = L.u;
}

// ---------------------------------------------------------------------------
// C = A @ B^T + bias via mma.sync fp16. three=1: Ah*Bh + Ah*Bl + Al*Bh;
// three=0: Ah*Bh + Ah*Bl. 128x128 CTA tile, 8 warps 2x4, 2-stage cp.async.
// mode: 0 = fp32 C, 1 = fp16 hi+lo splits, 2 = bf16 hi+lo splits.
// ---------------------------------------------------------------------------
#define LDA 40
#define STB (128*LDA*2)          // 10240 B per array
#define HG_SMEM (2*4*STB)        // 81920 B

struct GemmJob {
    const __half *Ah, *Al, *Bh, *Bl;
    const float* bias;
    float* C;
    void *Chi, *Clo;
    float* norm;
    int mode;
    int three;
};

__global__ __launch_bounds__(256) void hgemm_nt_mixed(
    GemmJob j0, GemmJob j1, GemmJob j2, int M, int N, int K)
{
    extern __shared__ __half smem[];
    const uint32_t uS = smem_u32(smem);
    const GemmJob jb = (blockIdx.z == 0) ? j0 : (blockIdx.z == 1) ? j1 : j2;

    const int tid = threadIdx.x, lane = tid & 31, wid = tid >> 5;
    const int wm = wid >> 2, wn = wid & 3;
    const int row0 = blockIdx.y * 128, col0 = blockIdx.x * 128;

    float acc[4][4][4];
#pragma unroll
    for (int i = 0; i < 4; i++)
#pragma unroll
        for (int j = 0; j < 4; j++)
#pragma unroll
            for (int f = 0; f < 4; f++) acc[i][j][f] = 0.0f;

    const int a_row = lane & 15, a_kg = lane >> 4;
    const int b_row = ((lane >> 4) & 1) * 8 + (lane & 7);
    const int b_kg  = (lane >> 3) & 1;

    const int gr = tid >> 2;
    const int gc = (tid & 3) * 8;

    const int NT = K / 32;

    auto load_st = [&](int s, int t) {
        const int k0 = t * 32;
        const uint32_t base = uS + s * 4 * STB;
#pragma unroll
        for (int pp = 0; pp < 2; pp++) {
            int r = pp * 64 + gr;
            uint32_t doff = (uint32_t)(r * LDA + gc) * 2;
            size_t ga = (size_t)(row0 + r) * K + k0 + gc;
            size_t gb = (size_t)(col0 + r) * K + k0 + gc;
            cpasync16(base + 0 * STB + doff, &jb.Ah[ga]);
            if (jb.three) cpasync16(base + 1 * STB + doff, &jb.Al[ga]);
            cpasync16(base + 2 * STB + doff, &jb.Bh[gb]);
            cpasync16(base + 3 * STB + doff, &jb.Bl[gb]);
        }
    };

    load_st(0, 0);
    CP_COMMIT();

    for (int t = 0; t < NT; t++) {
        CP_WAIT(0);
        __syncthreads();
        if (t + 1 < NT) {
            load_st((t + 1) & 1, t + 1);
            CP_COMMIT();
        }
        const uint32_t st = uS + (t & 1) * 4 * STB;
        const uint32_t sA_h = st, sA_l = st + STB, sB_h = st + 2 * STB, sB_l = st + 3 * STB;

#pragma unroll
        for (int kk = 0; kk < 2; kk++) {
            const uint32_t aoff = ((wm * 64 + a_row) * LDA + kk * 16 + a_kg * 8) * 2;
            const uint32_t boff0 = ((wn * 32 + b_row) * LDA + kk * 16 + b_kg * 8) * 2;
            const uint32_t boff1 = boff0 + 16 * LDA * 2;

            uint32_t bh_f[4][2], bl_f[4][2], af[4][4];
            {
                uint32_t tt[4];
                ldsm_x4(tt, sB_h + boff0);
                bh_f[0][0] = tt[0]; bh_f[0][1] = tt[1]; bh_f[1][0] = tt[2]; bh_f[1][1] = tt[3];
                ldsm_x4(tt, sB_h + boff1);
                bh_f[2][0] = tt[0]; bh_f[2][1] = tt[1]; bh_f[3][0] = tt[2]; bh_f[3][1] = tt[3];
                ldsm_x4(tt, sB_l + boff0);
                bl_f[0][0] = tt[0]; bl_f[0][1] = tt[1]; bl_f[1][0] = tt[2]; bl_f[1][1] = tt[3];
                ldsm_x4(tt, sB_l + boff1);
                bl_f[2][0] = tt[0]; bl_f[2][1] = tt[1]; bl_f[3][0] = tt[2]; bl_f[3][1] = tt[3];
            }
#pragma unroll
            for (int mi = 0; mi < 4; mi++)
                ldsm_x4(af[mi], sA_h + aoff + mi * 16 * LDA * 2);
#pragma unroll
            for (int mi = 0; mi < 4; mi++)
#pragma unroll
                for (int ni = 0; ni < 4; ni++)
                    mma_f16(acc[mi][ni], af[mi], bh_f[ni]);
#pragma unroll
            for (int mi = 0; mi < 4; mi++)
#pragma unroll
                for (int ni = 0; ni < 4; ni++)
                    mma_f16(acc[mi][ni], af[mi], bl_f[ni]);
            if (jb.three) {
#pragma unroll
                for (int mi = 0; mi < 4; mi++)
                    ldsm_x4(af[mi], sA_l + aoff + mi * 16 * LDA * 2);
#pragma unroll
                for (int mi = 0; mi < 4; mi++)
#pragma unroll
                    for (int ni = 0; ni < 4; ni++)
                        mma_f16(acc[mi][ni], af[mi], bh_f[ni]);
            }
        }
    }
    __syncthreads();

    const int erow = lane >> 2, ecol = (lane & 3) * 2;
    const int hh = (col0 + wn * 32) >> 6;
#pragma unroll
    for (int mi = 0; mi < 4; mi++) {
        float s0 = 0.0f, s1 = 0.0f;
#pragma unroll
        for (int ni = 0; ni < 4; ni++) {
            int rg = row0 + wm * 64 + mi * 16 + erow;
            int cg = col0 + wn * 32 + ni * 8 + ecol;
            float2 bb = *(const float2*)&jb.bias[cg];
            float o00 = acc[mi][ni][0] + bb.x, o01 = acc[mi][ni][1] + bb.y;
            float o10 = acc[mi][ni][2] + bb.x, o11 = acc[mi][ni][3] + bb.y;
            s0 += o00 * o00 + o01 * o01;
            s1 += o10 * o10 + o11 * o11;
            size_t i0 = (size_t)rg * N + cg, i1 = (size_t)(rg + 8) * N + cg;
            if (jb.mode == 0) {
                *(float2*)&jb.C[i0] = make_float2(o00, o01);
                *(float2*)&jb.C[i1] = make_float2(o10, o11);
            } else if (jb.mode == 1) {
                __half h00 = __float2half(o00), h01 = __float2half(o01);
                __half h10 = __float2half(o10), h11 = __float2half(o11);
                *(__half2*)((__half*)jb.Chi + i0) = __half2(h00, h01);
                *(__half2*)((__half*)jb.Chi + i1) = __half2(h10, h11);
                *(__half2*)((__half*)jb.Clo + i0) = __half2(
                    __float2half(o00 - __half2float(h00)),
                    __float2half(o01 - __half2float(h01)));
                *(__half2*)((__half*)jb.Clo + i1) = __half2(
                    __float2half(o10 - __half2float(h10)),
                    __float2half(o11 - __half2float(h11)));
            } else {
                __nv_bfloat16 h00 = __float2bfloat16(o00), h01 = __float2bfloat16(o01);
                __nv_bfloat16 h10 = __float2bfloat16(o10), h11 = __float2bfloat16(o11);
                *(__nv_bfloat162*)((__nv_bfloat16*)jb.Chi + i0) = __nv_bfloat162(h00, h01);
                *(__nv_bfloat162*)((__nv_bfloat16*)jb.Chi + i1) = __nv_bfloat162(h10, h11);
                *(__nv_bfloat162*)((__nv_bfloat16*)jb.Clo + i0) = __nv_bfloat162(
                    __float2bfloat16(o00 - __bfloat162float(h00)),
                    __float2bfloat16(o01 - __bfloat162float(h01)));
                *(__nv_bfloat162*)((__nv_bfloat16*)jb.Clo + i1) = __nv_bfloat162(
                    __float2bfloat16(o10 - __bfloat162float(h10)),
                    __float2bfloat16(o11 - __bfloat162float(h11)));
            }
        }
        if (jb.norm) {
            int rg = row0 + wm * 64 + mi * 16 + erow;
            atomicAdd(&jb.norm[(size_t)hh * CM + rg], s0);
            atomicAdd(&jb.norm[(size_t)hh * CM + rg + 8], s1);
        }
    }
}

// ---------------------------------------------------------------------------
// YAT flash attention: QK^T fp16 3-product (precise), PV bf16 3-product.
// 256 q-rows/CTA, 32 q-rows/warp. O written as fp16 hi only.
// ---------------------------------------------------------------------------
#define LDS 72
#define AQ_EL 18432
#define KV_EL 18432
#define ATTN_SMEM ((2*AQ_EL + 2*KV_EL)*2 + 512 + 128)   // 148096 B

__global__ void __launch_bounds__(256, 1) yat_attn_mma(
    const __half* __restrict__ Qhm, const __half* __restrict__ Qlm,
    const __half* __restrict__ Khm, const __half* __restrict__ Klm,
    const __nv_bfloat16* __restrict__ Vhm, const __nv_bfloat16* __restrict__ Vlm,
    const float* __restrict__ qn, const float* __restrict__ kn,
    __half* __restrict__ Ohm,
    const float* __restrict__ alphap)
{
    extern __shared__ __half sb[];
    const uint32_t uS = smem_u32(sb);
    const uint32_t uQh = uS, uQl = uS + AQ_EL * 2;
    const uint32_t uKV = uS + 2 * AQ_EL * 2;
    const uint32_t uKN = uS + (2 * AQ_EL + 2 * KV_EL) * 2;

    const int tid = threadIdx.x, lane = tid & 31, w = tid >> 5;
    const int g = lane >> 2, tg = lane & 3;
    const int b = blockIdx.z, h = blockIdx.y;
    const int q0 = blockIdx.x * 256;
    const size_t tokq = (size_t)b * CS + q0;

    const float scale = powf(8.0f / logf(65.0f), alphap[0]);

    {
        int c8 = tid & 7;
        int rb = tid >> 3;
#pragma unroll
        for (int i = 0; i < 8; i++) {
            int r = rb + i * 32;
            size_t gq = (tokq + r) * CE + h * CD + c8 * 8;
            *(uint4*)&sb[r * LDS + c8 * 8] = *(const uint4*)&Qhm[gq];
            *(uint4*)&sb[AQ_EL + r * LDS + c8 * 8] = *(const uint4*)&Qlm[gq];
        }
    }

    float sq[2][2];
#pragma unroll
    for (int mi = 0; mi < 2; mi++) {
        sq[mi][0] = qn[(size_t)h * CM + tokq + w * 32 + mi * 16 + g];
        sq[mi][1] = qn[(size_t)h * CM + tokq + w * 32 + mi * 16 + g + 8];
    }

    float l[2][2] = {{0.f, 0.f}, {0.f, 0.f}};
    float accO[2][8][4];
#pragma unroll
    for (int mi = 0; mi < 2; mi++)
#pragma unroll
        for (int i = 0; i < 8; i++)
#pragma unroll
            for (int j = 0; j < 4; j++) accO[mi][i][j] = 0.0f;

    const int a_row = lane & 15, a_kg = lane >> 4;
    const int b_row = ((lane >> 4) & 1) * 8 + (lane & 7);
    const int b_kg  = (lane >> 3) & 1;

    auto load_kv = [&](int stg, int t) {
        int r = tid >> 2, c2 = (tid & 3) * 2;
        size_t gk = ((size_t)b * CS + t * 64 + r) * CE + h * CD;
        const uint32_t sbase = uKV + (uint32_t)stg * KV_EL * 2u;
#pragma unroll
        for (int u = 0; u < 2; u++) {
            int cc = (c2 + u) * 8;
            uint32_t doff = (uint32_t)(r * LDS + cc) * 2;
            cpasync16(sbase + 0u * 9216u + doff, &Khm[gk + cc]);
            cpasync16(sbase + 1u * 9216u + doff, &Klm[gk + cc]);
            cpasync16(sbase + 2u * 9216u + doff, &Vhm[gk + cc]);
            cpasync16(sbase + 3u * 9216u + doff, &Vlm[gk + cc]);
        }
        if (tid < 16)
            cpasync16(uKN + (uint32_t)stg * 256u + tid * 16,
                      &kn[(size_t)h * CM + b * CS + t * 64 + tid * 4]);
    };

    load_kv(0, 0);
    CP_COMMIT();

    const int NT = CS / 64;
    for (int t = 0; t < NT; t++) {
        CP_WAIT(0);
        __syncthreads();
        if (t + 1 < NT) {
            load_kv((t + 1) & 1, t + 1);
            CP_COMMIT();
        }
        const uint32_t kb = uKV + (uint32_t)(t & 1) * KV_EL * 2u;
        const uint32_t uKh = kb, uKl = kb + 9216u, uVh = kb + 18432u, uVl = kb + 27648u;
        const float* skn = (const float*)((const char*)sb + (2 * AQ_EL + 2 * KV_EL) * 2 + (t & 1) * 256);

        float sS[2][8][4];
#pragma unroll
        for (int mi = 0; mi < 2; mi++)
#pragma unroll
            for (int i = 0; i < 8; i++)
#pragma unroll
                for (int j = 0; j < 4; j++) sS[mi][i][j] = 0.0f;

#pragma unroll
        for (int kk = 0; kk < 4; kk++) {
            uint32_t ah[2][4], al[2][4];
#pragma unroll
            for (int mi = 0; mi < 2; mi++) {
                const uint32_t aoff = ((w * 32 + mi * 16 + a_row) * LDS + kk * 16 + a_kg * 8) * 2;
                ldsm_x4(ah[mi], uQh + aoff);
                ldsm_x4(al[mi], uQl + aoff);
            }
#pragma unroll
            for (int nb = 0; nb < 4; nb++) {
                const uint32_t boff = ((nb * 16 + b_row) * LDS + kk * 16 + b_kg * 8) * 2;
                uint32_t th[4], tl[4];
                ldsm_x4(th, uKh + boff);
                ldsm_x4(tl, uKl + boff);
#pragma unroll
                for (int mi = 0; mi < 2; mi++) {
                    mma_f16(sS[mi][2 * nb],     ah[mi], th);
                    mma_f16(sS[mi][2 * nb + 1], ah[mi], th + 2);
                    mma_f16(sS[mi][2 * nb],     ah[mi], tl);
                    mma_f16(sS[mi][2 * nb + 1], ah[mi], tl + 2);
                    mma_f16(sS[mi][2 * nb],     al[mi], th);
                    mma_f16(sS[mi][2 * nb + 1], al[mi], th + 2);
                }
            }
        }

        // YAT score -> exp (no max-shift; bounded scores; clamp@75 guard)
#pragma unroll
        for (int mi = 0; mi < 2; mi++) {
#pragma unroll
            for (int ni = 0; ni < 8; ni++) {
                int col = ni * 8 + tg * 2;
                float k0 = skn[col], k1 = skn[col + 1];
                float qk, d, s;
                qk = sS[mi][ni][0]; d = sq[mi][0] + k0 - 2.0f * qk + YAT_EPS;
                s = fminf(scale * (qk * qk) * rcp_fma(d), 75.0f);
                sS[mi][ni][0] = __expf(s); l[mi][0] += sS[mi][ni][0];
                qk = sS[mi][ni][1]; d = sq[mi][0] + k1 - 2.0f * qk + YAT_EPS;
                s = fminf(scale * (qk * qk) * rcp_fma(d), 75.0f);
                sS[mi][ni][1] = __expf(s); l[mi][0] += sS[mi][ni][1];
                qk = sS[mi][ni][2]; d = sq[mi][1] + k0 - 2.0f * qk + YAT_EPS;
                s = fminf(scale * (qk * qk) * rcp_fma(d), 75.0f);
                sS[mi][ni][2] = __expf(s); l[mi][1] += sS[mi][ni][2];
                qk = sS[mi][ni][3]; d = sq[mi][1] + k1 - 2.0f * qk + YAT_EPS;
                s = fminf(scale * (qk * qk) * rcp_fma(d), 75.0f);
                sS[mi][ni][3] = __expf(s); l[mi][1] += sS[mi][ni][3];
            }
        }

        // O += P @ V (bf16 3-product; P range needs bf16)
#pragma unroll
        for (int kk = 0; kk < 4; kk++) {
            uint32_t ph[2][4], pl[2][4];
#pragma unroll
            for (int mi = 0; mi < 2; mi++) {
                const float* e = sS[mi][2 * kk];
                const float* f = sS[mi][2 * kk + 1];
                uint32_t u0, u1;
                float h0, h1;
                u0 = __float_as_uint(e[0]); u1 = __float_as_uint(e[1]);
                ph[mi][0] = prmt7632(u0, u1);
                h0 = __uint_as_float(u0 & 0xffff0000u); h1 = __uint_as_float(u1 & 0xffff0000u);
                pl[mi][0] = pkbf16x2(e[0] - h0, e[1] - h1);
                u0 = __float_as_uint(e[2]); u1 = __float_as_uint(e[3]);
                ph[mi][1] = prmt7632(u0, u1);
                h0 = __uint_as_float(u0 & 0xffff0000u); h1 = __uint_as_float(u1 & 0xffff0000u);
                pl[mi][1] = pkbf16x2(e[2] - h0, e[3] - h1);
                u0 = __float_as_uint(f[0]); u1 = __float_as_uint(f[1]);
                ph[mi][2] = prmt7632(u0, u1);
                h0 = __uint_as_float(u0 & 0xffff0000u); h1 = __uint_as_float(u1 & 0xffff0000u);
                pl[mi][2] = pkbf16x2(f[0] - h0, f[1] - h1);
                u0 = __float_as_uint(f[2]); u1 = __float_as_uint(f[3]);
                ph[mi][3] = prmt7632(u0, u1);
                h0 = __uint_as_float(u0 & 0xffff0000u); h1 = __uint_as_float(u1 & 0xffff0000u);
                pl[mi][3] = pkbf16x2(f[2] - h0, f[3] - h1);
            }
#pragma unroll
            for (int db = 0; db < 4; db++) {
                const uint32_t voff = ((kk * 16 + (lane & 15)) * LDS + db * 16 + (lane >> 4) * 8) * 2;
                uint32_t th[4], tl[4];
                ldsm_x4_t(th, uVh + voff);
                ldsm_x4_t(tl, uVl + voff);
#pragma unroll
                for (int mi = 0; mi < 2; mi++) {
                    mma_bf16(accO[mi][2 * db],     ph[mi], th);
                    mma_bf16(accO[mi][2 * db + 1], ph[mi], th + 2);
                    mma_bf16(accO[mi][2 * db],     ph[mi], tl);
                    mma_bf16(accO[mi][2 * db + 1], ph[mi], tl + 2);
                    mma_bf16(accO[mi][2 * db],     pl[mi], th);
                    mma_bf16(accO[mi][2 * db + 1], pl[mi], th + 2);
                }
            }
        }
    }

#pragma unroll
    for (int off = 1; off <= 2; off <<= 1) {
#pragma unroll
        for (int mi = 0; mi < 2; mi++) {
            l[mi][0] += __shfl_xor_sync(0xffffffffu, l[mi][0], off);
            l[mi][1] += __shfl_xor_sync(0xffffffffu, l[mi][1], off);
        }
    }

#pragma unroll
    for (int mi = 0; mi < 2; mi++) {
        float inv0 = rcp_fma(l[mi][0]), inv1 = rcp_fma(l[mi][1]);
        size_t ro = (tokq + w * 32 + mi * 16 + g) * CE + h * CD;
#pragma unroll
        for (int ni = 0; ni < 8; ni++) {
            int c = ni * 8 + tg * 2;
            *(uint32_t*)&Ohm[ro + c] =
                pkf16x2(accO[mi][ni][0] * inv0, accO[mi][ni][1] * inv0);
            *(uint32_t*)&Ohm[ro + 8 * CE + c] =
                pkf16x2(accO[mi][ni][2] * inv1, accO[mi][ni][3] * inv1);
        }
    }
}

// ---------------------------------------------------------------------------
extern "C" void kernel_launch(void* const* d_in, const int* in_sizes, int n_in,
                              void* d_out, int out_size)
{
    (void)in_sizes; (void)n_in; (void)out_size;
    const float* query = (const float*)d_in[0];
    const float* Wq    = (const float*)d_in[1];
    const float* bq    = (const float*)d_in[2];
    const float* Wk    = (const float*)d_in[3];
    const float* bk    = (const float*)d_in[4];
    const float* Wv    = (const float*)d_in[5];
    const float* bv    = (const float*)d_in[6];
    const float* Wo    = (const float*)d_in[7];
    const float* bo    = (const float*)d_in[8];
    const float* alpha = (const float*)d_in[9];

    float *qn, *kn;
    cudaGetSymbolAddress((void**)&qn, g_qn);
    cudaGetSymbolAddress((void**)&kn, g_kn);
    __half *xh, *xl, *oh, *wqh, *wql, *wkh, *wkl, *wvh, *wvl, *woh, *wol;
    __half *aqh, *aql, *akh, *akl;
    __nv_bfloat16 *avh, *avl;
    cudaGetSymbolAddress((void**)&xh, g_xh);   cudaGetSymbolAddress((void**)&xl, g_xl);
    cudaGetSymbolAddress((void**)&oh, g_oh);
    cudaGetSymbolAddress((void**)&wqh, g_wqh); cudaGetSymbolAddress((void**)&wql, g_wql);
    cudaGetSymbolAddress((void**)&wkh, g_wkh); cudaGetSymbolAddress((void**)&wkl, g_wkl);
    cudaGetSymbolAddress((void**)&wvh, g_wvh); cudaGetSymbolAddress((void**)&wvl, g_wvl);
    cudaGetSymbolAddress((void**)&woh, g_woh); cudaGetSymbolAddress((void**)&wol, g_wol);
    cudaGetSymbolAddress((void**)&aqh, g_aqh); cudaGetSymbolAddress((void**)&aql, g_aql);
    cudaGetSymbolAddress((void**)&akh, g_akh); cudaGetSymbolAddress((void**)&akl, g_akl);
    cudaGetSymbolAddress((void**)&avh, g_avh); cudaGetSymbolAddress((void**)&avl, g_avl);

    const int nx4 = CM * CE / 4;
    const int nw4 = CE * CE / 4;
    zero_norms<<<CH * CM / 256, 256>>>(qn, kn);
    {
        SplitJob jx = {query, xh, xl};
        split_f16_multi<<<dim3(nx4 / 256, 1), 256>>>(jx, jx, jx, jx, nx4);
        SplitJob jq = {Wq, wqh, wql}, jk = {Wk, wkh, wkl}, jv = {Wv, wvh, wvl}, jo = {Wo, woh, wol};
        split_f16_multi<<<dim3(nw4 / 256, 4), 256>>>(jq, jk, jv, jo, nw4);
    }

    cudaFuncSetAttribute(hgemm_nt_mixed, cudaFuncAttributeMaxDynamicSharedMemorySize, HG_SMEM);
    {
        // Q,K: fp16 3-product (feeds exp-amplified YAT score). V: fp16 2-product.
        GemmJob jq = {xh, xl, wqh, wql, bq, nullptr, aqh, aql, qn, 1, 1};
        GemmJob jk = {xh, xl, wkh, wkl, bk, nullptr, akh, akl, kn, 1, 1};
        GemmJob jv = {xh, xl, wvh, wvl, bv, nullptr, avh, avl, nullptr, 2, 0};
        hgemm_nt_mixed<<<dim3(CE / 128, CM / 128, 3), 256, HG_SMEM>>>(jq, jk, jv, CM, CE, CE);
    }

    cudaFuncSetAttribute(yat_attn_mma, cudaFuncAttributeMaxDynamicSharedMemorySize, ATTN_SMEM);
    yat_attn_mma<<<dim3(CS / 256, CH, CB), 256, ATTN_SMEM>>>(
        aqh, aql, akh, akl, avh, avl, qn, kn, oh, alpha);

    {
        // Output projection: fp16 2-product (linear path)
        GemmJob jo = {oh, nullptr, woh, wol, bo, (float*)d_out, nullptr, nullptr, nullptr, 0, 0};
        hgemm_nt_mixed<<<dim3(CE / 128, CM / 128, 1), 256, HG_SMEM>>>(jo, jo, jo, CM, CE, CE);
    }
}

// round 17
// speedup vs baseline: 1.0920x; 1.0049x over previous
#include <cuda_runtime.h>
#include <cuda_bf16.h>
#include <cuda_fp16.h>
#include <math.h>
#include <stdint.h>

#define CB 2
#define CS 2048
#define CE 1024
#define CH 16
#define CD 64
#define CM (CB*CS)          // 4096 tokens
#define YAT_EPS 1e-5f

__device__ __forceinline__ uint32_t smem_u32(const void* p) {
    uint32_t a;
    asm("{ .reg .u64 t; cvta.to.shared.u64 t, %1; cvt.u32.u64 %0, t; }" : "=r"(a) : "l"(p));
    return a;
}

// ---- mma.sync / ldmatrix / cp.async helpers (portable to non-'a' sm_103) ----
__device__ __forceinline__ void ldsm_x4(uint32_t* r, uint32_t addr) {
    asm volatile("ldmatrix.sync.aligned.m8n8.x4.shared.b16 {%0,%1,%2,%3}, [%4];"
        : "=r"(r[0]), "=r"(r[1]), "=r"(r[2]), "=r"(r[3]) : "r"(addr));
}
__device__ __forceinline__ void ldsm_x4_t(uint32_t* r, uint32_t addr) {
    asm volatile("ldmatrix.sync.aligned.m8n8.x4.trans.shared.b16 {%0,%1,%2,%3}, [%4];"
        : "=r"(r[0]), "=r"(r[1]), "=r"(r[2]), "=r"(r[3]) : "r"(addr));
}
__device__ __forceinline__ void mma_bf16(float* c, const uint32_t* a, const uint32_t* b) {
    asm volatile(
        "mma.sync.aligned.m16n8k16.row.col.f32.bf16.bf16.f32 "
        "{%0,%1,%2,%3}, {%4,%5,%6,%7}, {%8,%9}, {%0,%1,%2,%3};"
        : "+f"(c[0]), "+f"(c[1]), "+f"(c[2]), "+f"(c[3])
        : "r"(a[0]), "r"(a[1]), "r"(a[2]), "r"(a[3]), "r"(b[0]), "r"(b[1]));
}
__device__ __forceinline__ void mma_f16(float* c, const uint32_t* a, const uint32_t* b) {
    asm volatile(
        "mma.sync.aligned.m16n8k16.row.col.f32.f16.f16.f32 "
        "{%0,%1,%2,%3}, {%4,%5,%6,%7}, {%8,%9}, {%0,%1,%2,%3};"
        : "+f"(c[0]), "+f"(c[1]), "+f"(c[2]), "+f"(c[3])
        : "r"(a[0]), "r"(a[1]), "r"(a[2]), "r"(a[3]), "r"(b[0]), "r"(b[1]));
}
__device__ __forceinline__ uint32_t prmt7632(uint32_t a, uint32_t b) {
    uint32_t r; asm("prmt.b32 %0, %1, %2, 0x7632;" : "=r"(r) : "r"(a), "r"(b)); return r;
}
__device__ __forceinline__ uint32_t pkbf16x2(float lo, float hi) {
    uint32_t r; asm("cvt.rn.bf16x2.f32 %0, %1, %2;" : "=r"(r) : "f"(hi), "f"(lo)); return r;
}
__device__ __forceinline__ uint32_t pkf16x2(float lo, float hi) {
    uint32_t r; asm("cvt.rn.f16x2.f32 %0, %1, %2;" : "=r"(r) : "f"(hi), "f"(lo)); return r;
}
__device__ __forceinline__ void cpasync16(uint32_t dst, const void* src) {
    asm volatile("cp.async.cg.shared.global [%0], [%1], 16;" :: "r"(dst), "l"(src));
}
#define CP_COMMIT() asm volatile("cp.async.commit_group;" ::: "memory")
#define CP_WAIT(n)  asm volatile("cp.async.wait_group %0;" :: "n"(n) : "memory")

// FMA-pipe reciprocal (no MUFU): bit-hack seed + 2 Newton steps.
__device__ __forceinline__ float rcp_fma(float d) {
    float r = __uint_as_float(0x7EF311C3u - __float_as_uint(d));
    r = r * __fmaf_rn(-d, r, 2.0f);
    r = r * __fmaf_rn(-d, r, 2.0f);
    return r;
}

// ---- Scratch (__device__ globals; allocation-free rule) ----
__device__ __half g_xh[(size_t)CM*CE], g_xl[(size_t)CM*CE];
__device__ __half g_oh[(size_t)CM*CE];
__device__ __half g_wqh[(size_t)CE*CE], g_wql[(size_t)CE*CE];
__device__ __half g_wkh[(size_t)CE*CE], g_wkl[(size_t)CE*CE];
__device__ __half g_wvh[(size_t)CE*CE], g_wvl[(size_t)CE*CE];
__device__ __half g_woh[(size_t)CE*CE], g_wol[(size_t)CE*CE];
__device__ __half g_aqh[(size_t)CM*CE], g_aql[(size_t)CM*CE];
__device__ __half g_akh[(size_t)CM*CE], g_akl[(size_t)CM*CE];
__device__ __nv_bfloat16 g_avh[(size_t)CM*CE], g_avl[(size_t)CM*CE];
__device__ float g_qn[(size_t)CH*CM];
__device__ float g_kn[(size_t)CH*CM];

// ---------------------------------------------------------------------------
// Fused prep: y=0 -> x split; y=1..4 -> weight splits (excess blocks of y=1
// zero the norm arrays); all in one launch.
// ---------------------------------------------------------------------------
struct SplitJob { const float* x; __half* hi; __half* lo; };

__global__ __launch_bounds__(256) void prep_all(
    SplitJob jx, SplitJob j1, SplitJob j2, SplitJob j3, SplitJob j4,
    float* qn, float* kn, int nx4, int nw4)
{
    int i = blockIdx.x * blockDim.x + threadIdx.x;
    int y = blockIdx.y;
    SplitJob j;
    int n4;
    if (y == 0) { j = jx; n4 = nx4; }
    else if (y == 1) { j = j1; n4 = nw4; }
    else if (y == 2) { j = j2; n4 = nw4; }
    else if (y == 3) { j = j3; n4 = nw4; }
    else { j = j4; n4 = nw4; }

    if (i >= n4) {
        if (y == 1) {
            int zi = i - n4;
            if (zi < CH * CM / 4) {
                ((float4*)qn)[zi] = make_float4(0.f, 0.f, 0.f, 0.f);
                ((float4*)kn)[zi] = make_float4(0.f, 0.f, 0.f, 0.f);
            }
        }
        return;
    }
    float4 v = ((const float4*)j.x)[i];
    union { __half b[4]; uint2 u; } H, L;
    float a[4] = {v.x, v.y, v.z, v.w};
#pragma unroll
    for (int jj = 0; jj < 4; jj++) {
        __half h = __float2half(a[jj]);
        H.b[jj] = h;
        L.b[jj] = __float2half(a[jj] - __half2float(h));
    }
    ((uint2*)j.hi)[i] = H.u;
    ((uint2*)j.lo)[i] = L.u;
}

// ---------------------------------------------------------------------------
// C = A @ B^T + bias via mma.sync fp16. three=1: Ah*Bh + Ah*Bl + Al*Bh;
// three=0: Ah*Bh + Ah*Bl. 128x128 CTA tile, 8 warps 2x4, 2-stage cp.async.
// mode: 0 = fp32 C, 1 = fp16 hi+lo splits, 2 = bf16 hi+lo splits.
// ---------------------------------------------------------------------------
#define LDA 40
#define STB (128*LDA*2)          // 10240 B per array
#define HG_SMEM (2*4*STB)        // 81920 B

struct GemmJob {
    const __half *Ah, *Al, *Bh, *Bl;
    const float* bias;
    float* C;
    void *Chi, *Clo;
    float* norm;
    int mode;
    int three;
};

__global__ __launch_bounds__(256) void hgemm_nt_mixed(
    GemmJob j0, GemmJob j1, GemmJob j2, int M, int N, int K)
{
    extern __shared__ __half smem[];
    const uint32_t uS = smem_u32(smem);
    const GemmJob jb = (blockIdx.z == 0) ? j0 : (blockIdx.z == 1) ? j1 : j2;

    const int tid = threadIdx.x, lane = tid & 31, wid = tid >> 5;
    const int wm = wid >> 2, wn = wid & 3;
    const int row0 = blockIdx.y * 128, col0 = blockIdx.x * 128;

    float acc[4][4][4];
#pragma unroll
    for (int i = 0; i < 4; i++)
#pragma unroll
        for (int j = 0; j < 4; j++)
#pragma unroll
            for (int f = 0; f < 4; f++) acc[i][j][f] = 0.0f;

    const int a_row = lane & 15, a_kg = lane >> 4;
    const int b_row = ((lane >> 4) & 1) * 8 + (lane & 7);
    const int b_kg  = (lane >> 3) & 1;

    const int gr = tid >> 2;
    const int gc = (tid & 3) * 8;

    const int NT = K / 32;

    auto load_st = [&](int s, int t) {
        const int k0 = t * 32;
        const uint32_t base = uS + s * 4 * STB;
#pragma unroll
        for (int pp = 0; pp < 2; pp++) {
            int r = pp * 64 + gr;
            uint32_t doff = (uint32_t)(r * LDA + gc) * 2;
            size_t ga = (size_t)(row0 + r) * K + k0 + gc;
            size_t gb = (size_t)(col0 + r) * K + k0 + gc;
            cpasync16(base + 0 * STB + doff, &jb.Ah[ga]);
            if (jb.three) cpasync16(base + 1 * STB + doff, &jb.Al[ga]);
            cpasync16(base + 2 * STB + doff, &jb.Bh[gb]);
            cpasync16(base + 3 * STB + doff, &jb.Bl[gb]);
        }
    };

    load_st(0, 0);
    CP_COMMIT();

    for (int t = 0; t < NT; t++) {
        CP_WAIT(0);
        __syncthreads();
        if (t + 1 < NT) {
            load_st((t + 1) & 1, t + 1);
            CP_COMMIT();
        }
        const uint32_t st = uS + (t & 1) * 4 * STB;
        const uint32_t sA_h = st, sA_l = st + STB, sB_h = st + 2 * STB, sB_l = st + 3 * STB;

#pragma unroll
        for (int kk = 0; kk < 2; kk++) {
            const uint32_t aoff = ((wm * 64 + a_row) * LDA + kk * 16 + a_kg * 8) * 2;
            const uint32_t boff0 = ((wn * 32 + b_row) * LDA + kk * 16 + b_kg * 8) * 2;
            const uint32_t boff1 = boff0 + 16 * LDA * 2;

            uint32_t bh_f[4][2], bl_f[4][2], af[4][4];
            {
                uint32_t tt[4];
                ldsm_x4(tt, sB_h + boff0);
                bh_f[0][0] = tt[0]; bh_f[0][1] = tt[1]; bh_f[1][0] = tt[2]; bh_f[1][1] = tt[3];
                ldsm_x4(tt, sB_h + boff1);
                bh_f[2][0] = tt[0]; bh_f[2][1] = tt[1]; bh_f[3][0] = tt[2]; bh_f[3][1] = tt[3];
                ldsm_x4(tt, sB_l + boff0);
                bl_f[0][0] = tt[0]; bl_f[0][1] = tt[1]; bl_f[1][0] = tt[2]; bl_f[1][1] = tt[3];
                ldsm_x4(tt, sB_l + boff1);
                bl_f[2][0] = tt[0]; bl_f[2][1] = tt[1]; bl_f[3][0] = tt[2]; bl_f[3][1] = tt[3];
            }
#pragma unroll
            for (int mi = 0; mi < 4; mi++)
                ldsm_x4(af[mi], sA_h + aoff + mi * 16 * LDA * 2);
#pragma unroll
            for (int mi = 0; mi < 4; mi++)
#pragma unroll
                for (int ni = 0; ni < 4; ni++)
                    mma_f16(acc[mi][ni], af[mi], bh_f[ni]);
#pragma unroll
            for (int mi = 0; mi < 4; mi++)
#pragma unroll
                for (int ni = 0; ni < 4; ni++)
                    mma_f16(acc[mi][ni], af[mi], bl_f[ni]);
            if (jb.three) {
#pragma unroll
                for (int mi = 0; mi < 4; mi++)
                    ldsm_x4(af[mi], sA_l + aoff + mi * 16 * LDA * 2);
#pragma unroll
                for (int mi = 0; mi < 4; mi++)
#pragma unroll
                    for (int ni = 0; ni < 4; ni++)
                        mma_f16(acc[mi][ni], af[mi], bh_f[ni]);
            }
        }
    }
    __syncthreads();

    const int erow = lane >> 2, ecol = (lane & 3) * 2;
    const int hh = (col0 + wn * 32) >> 6;
#pragma unroll
    for (int mi = 0; mi < 4; mi++) {
        float s0 = 0.0f, s1 = 0.0f;
#pragma unroll
        for (int ni = 0; ni < 4; ni++) {
            int rg = row0 + wm * 64 + mi * 16 + erow;
            int cg = col0 + wn * 32 + ni * 8 + ecol;
            float2 bb = *(const float2*)&jb.bias[cg];
            float o00 = acc[mi][ni][0] + bb.x, o01 = acc[mi][ni][1] + bb.y;
            float o10 = acc[mi][ni][2] + bb.x, o11 = acc[mi][ni][3] + bb.y;
            s0 += o00 * o00 + o01 * o01;
            s1 += o10 * o10 + o11 * o11;
            size_t i0 = (size_t)rg * N + cg, i1 = (size_t)(rg + 8) * N + cg;
            if (jb.mode == 0) {
                *(float2*)&jb.C[i0] = make_float2(o00, o01);
                *(float2*)&jb.C[i1] = make_float2(o10, o11);
            } else if (jb.mode == 1) {
                __half h00 = __float2half(o00), h01 = __float2half(o01);
                __half h10 = __float2half(o10), h11 = __float2half(o11);
                *(__half2*)((__half*)jb.Chi + i0) = __half2(h00, h01);
                *(__half2*)((__half*)jb.Chi + i1) = __half2(h10, h11);
                *(__half2*)((__half*)jb.Clo + i0) = __half2(
                    __float2half(o00 - __half2float(h00)),
                    __float2half(o01 - __half2float(h01)));
                *(__half2*)((__half*)jb.Clo + i1) = __half2(
                    __float2half(o10 - __half2float(h10)),
                    __float2half(o11 - __half2float(h11)));
            } else {
                __nv_bfloat16 h00 = __float2bfloat16(o00), h01 = __float2bfloat16(o01);
                __nv_bfloat16 h10 = __float2bfloat16(o10), h11 = __float2bfloat16(o11);
                *(__nv_bfloat162*)((__nv_bfloat16*)jb.Chi + i0) = __nv_bfloat162(h00, h01);
                *(__nv_bfloat162*)((__nv_bfloat16*)jb.Chi + i1) = __nv_bfloat162(h10, h11);
                *(__nv_bfloat162*)((__nv_bfloat16*)jb.Clo + i0) = __nv_bfloat162(
                    __float2bfloat16(o00 - __bfloat162float(h00)),
                    __float2bfloat16(o01 - __bfloat162float(h01)));
                *(__nv_bfloat162*)((__nv_bfloat16*)jb.Clo + i1) = __nv_bfloat162(
                    __float2bfloat16(o10 - __bfloat162float(h10)),
                    __float2bfloat16(o11 - __bfloat162float(h11)));
            }
        }
        if (jb.norm) {
            int rg = row0 + wm * 64 + mi * 16 + erow;
            atomicAdd(&jb.norm[(size_t)hh * CM + rg], s0);
            atomicAdd(&jb.norm[(size_t)hh * CM + rg + 8], s1);
        }
    }
}

// ---------------------------------------------------------------------------
// YAT flash attention: QK^T fp16 3-product, PV bf16 3-product.
// 256 q-rows/CTA, 32 q-rows/warp. Q tile loaded via cp.async (prologue overlap).
// ---------------------------------------------------------------------------
#define LDS 72
#define AQ_EL 18432
#define KV_EL 18432
#define ATTN_SMEM ((2*AQ_EL + 2*KV_EL)*2 + 512 + 128)   // 148096 B

__global__ void __launch_bounds__(256, 1) yat_attn_mma(
    const __half* __restrict__ Qhm, const __half* __restrict__ Qlm,
    const __half* __restrict__ Khm, const __half* __restrict__ Klm,
    const __nv_bfloat16* __restrict__ Vhm, const __nv_bfloat16* __restrict__ Vlm,
    const float* __restrict__ qn, const float* __restrict__ kn,
    __half* __restrict__ Ohm,
    const float* __restrict__ alphap)
{
    extern __shared__ __half sb[];
    const uint32_t uS = smem_u32(sb);
    const uint32_t uQh = uS, uQl = uS + AQ_EL * 2;
    const uint32_t uKV = uS + 2 * AQ_EL * 2;
    const uint32_t uKN = uS + (2 * AQ_EL + 2 * KV_EL) * 2;

    const int tid = threadIdx.x, lane = tid & 31, w = tid >> 5;
    const int g = lane >> 2, tg = lane & 3;
    const int b = blockIdx.z, h = blockIdx.y;
    const int q0 = blockIdx.x * 256;
    const size_t tokq = (size_t)b * CS + q0;

    const float scale = powf(8.0f / logf(65.0f), alphap[0]);

    // Q tile via cp.async (overlaps with first KV stage)
    {
        int c8 = tid & 7;
        int rb = tid >> 3;
#pragma unroll
        for (int i = 0; i < 8; i++) {
            int r = rb + i * 32;
            size_t gq = (tokq + r) * CE + h * CD + c8 * 8;
            uint32_t doff = (uint32_t)(r * LDS + c8 * 8) * 2;
            cpasync16(uQh + doff, &Qhm[gq]);
            cpasync16(uQl + doff, &Qlm[gq]);
        }
    }

    float sq[2][2];
#pragma unroll
    for (int mi = 0; mi < 2; mi++) {
        sq[mi][0] = qn[(size_t)h * CM + tokq + w * 32 + mi * 16 + g];
        sq[mi][1] = qn[(size_t)h * CM + tokq + w * 32 + mi * 16 + g + 8];
    }

    float l[2][2] = {{0.f, 0.f}, {0.f, 0.f}};
    float accO[2][8][4];
#pragma unroll
    for (int mi = 0; mi < 2; mi++)
#pragma unroll
        for (int i = 0; i < 8; i++)
#pragma unroll
            for (int j = 0; j < 4; j++) accO[mi][i][j] = 0.0f;

    const int a_row = lane & 15, a_kg = lane >> 4;
    const int b_row = ((lane >> 4) & 1) * 8 + (lane & 7);
    const int b_kg  = (lane >> 3) & 1;

    auto load_kv = [&](int stg, int t) {
        int r = tid >> 2, c2 = (tid & 3) * 2;
        size_t gk = ((size_t)b * CS + t * 64 + r) * CE + h * CD;
        const uint32_t sbase = uKV + (uint32_t)stg * KV_EL * 2u;
#pragma unroll
        for (int u = 0; u < 2; u++) {
            int cc = (c2 + u) * 8;
            uint32_t doff = (uint32_t)(r * LDS + cc) * 2;
            cpasync16(sbase + 0u * 9216u + doff, &Khm[gk + cc]);
            cpasync16(sbase + 1u * 9216u + doff, &Klm[gk + cc]);
            cpasync16(sbase + 2u * 9216u + doff, &Vhm[gk + cc]);
            cpasync16(sbase + 3u * 9216u + doff, &Vlm[gk + cc]);
        }
        if (tid < 16)
            cpasync16(uKN + (uint32_t)stg * 256u + tid * 16,
                      &kn[(size_t)h * CM + b * CS + t * 64 + tid * 4]);
    };

    load_kv(0, 0);
    CP_COMMIT();

    const int NT = CS / 64;
    for (int t = 0; t < NT; t++) {
        CP_WAIT(0);
        __syncthreads();
        if (t + 1 < NT) {
            load_kv((t + 1) & 1, t + 1);
            CP_COMMIT();
        }
        const uint32_t kb = uKV + (uint32_t)(t & 1) * KV_EL * 2u;
        const uint32_t uKh = kb, uKl = kb + 9216u, uVh = kb + 18432u, uVl = kb + 27648u;
        const float* skn = (const float*)((const char*)sb + (2 * AQ_EL + 2 * KV_EL) * 2 + (t & 1) * 256);

        float sS[2][8][4];
#pragma unroll
        for (int mi = 0; mi < 2; mi++)
#pragma unroll
            for (int i = 0; i < 8; i++)
#pragma unroll
                for (int j = 0; j < 4; j++) sS[mi][i][j] = 0.0f;

#pragma unroll
        for (int kk = 0; kk < 4; kk++) {
            uint32_t ah[2][4], al[2][4];
#pragma unroll
            for (int mi = 0; mi < 2; mi++) {
                const uint32_t aoff = ((w * 32 + mi * 16 + a_row) * LDS + kk * 16 + a_kg * 8) * 2;
                ldsm_x4(ah[mi], uQh + aoff);
                ldsm_x4(al[mi], uQl + aoff);
            }
#pragma unroll
            for (int nb = 0; nb < 4; nb++) {
                const uint32_t boff = ((nb * 16 + b_row) * LDS + kk * 16 + b_kg * 8) * 2;
                uint32_t th[4], tl[4];
                ldsm_x4(th, uKh + boff);
                ldsm_x4(tl, uKl + boff);
#pragma unroll
                for (int mi = 0; mi < 2; mi++) {
                    mma_f16(sS[mi][2 * nb],     ah[mi], th);
                    mma_f16(sS[mi][2 * nb + 1], ah[mi], th + 2);
                    mma_f16(sS[mi][2 * nb],     ah[mi], tl);
                    mma_f16(sS[mi][2 * nb + 1], ah[mi], tl + 2);
                    mma_f16(sS[mi][2 * nb],     al[mi], th);
                    mma_f16(sS[mi][2 * nb + 1], al[mi], th + 2);
                }
            }
        }

        // YAT score -> exp (no max-shift; bounded scores; clamp@75 guard)
#pragma unroll
        for (int mi = 0; mi < 2; mi++) {
#pragma unroll
            for (int ni = 0; ni < 8; ni++) {
                int col = ni * 8 + tg * 2;
                float k0 = skn[col], k1 = skn[col + 1];
                float qk, d, s;
                qk = sS[mi][ni][0]; d = sq[mi][0] + k0 - 2.0f * qk + YAT_EPS;
                s = fminf(scale * (qk * qk) * rcp_fma(d), 75.0f);
                sS[mi][ni][0] = __expf(s); l[mi][0] += sS[mi][ni][0];
                qk = sS[mi][ni][1]; d = sq[mi][0] + k1 - 2.0f * qk + YAT_EPS;
                s = fminf(scale * (qk * qk) * rcp_fma(d), 75.0f);
                sS[mi][ni][1] = __expf(s); l[mi][0] += sS[mi][ni][1];
                qk = sS[mi][ni][2]; d = sq[mi][1] + k0 - 2.0f * qk + YAT_EPS;
                s = fminf(scale * (qk * qk) * rcp_fma(d), 75.0f);
                sS[mi][ni][2] = __expf(s); l[mi][1] += sS[mi][ni][2];
                qk = sS[mi][ni][3]; d = sq[mi][1] + k1 - 2.0f * qk + YAT_EPS;
                s = fminf(scale * (qk * qk) * rcp_fma(d), 75.0f);
                sS[mi][ni][3] = __expf(s); l[mi][1] += sS[mi][ni][3];
            }
        }

        // O += P @ V (bf16 3-product; P precision requires the Pl term)
#pragma unroll
        for (int kk = 0; kk < 4; kk++) {
            uint32_t ph[2][4], pl[2][4];
#pragma unroll
            for (int mi = 0; mi < 2; mi++) {
                const float* e = sS[mi][2 * kk];
                const float* f = sS[mi][2 * kk + 1];
                uint32_t u0, u1;
                float h0, h1;
                u0 = __float_as_uint(e[0]); u1 = __float_as_uint(e[1]);
                ph[mi][0] = prmt7632(u0, u1);
                h0 = __uint_as_float(u0 & 0xffff0000u); h1 = __uint_as_float(u1 & 0xffff0000u);
                pl[mi][0] = pkbf16x2(e[0] - h0, e[1] - h1);
                u0 = __float_as_uint(e[2]); u1 = __float_as_uint(e[3]);
                ph[mi][1] = prmt7632(u0, u1);
                h0 = __uint_as_float(u0 & 0xffff0000u); h1 = __uint_as_float(u1 & 0xffff0000u);
                pl[mi][1] = pkbf16x2(e[2] - h0, e[3] - h1);
                u0 = __float_as_uint(f[0]); u1 = __float_as_uint(f[1]);
                ph[mi][2] = prmt7632(u0, u1);
                h0 = __uint_as_float(u0 & 0xffff0000u); h1 = __uint_as_float(u1 & 0xffff0000u);
                pl[mi][2] = pkbf16x2(f[0] - h0, f[1] - h1);
                u0 = __float_as_uint(f[2]); u1 = __float_as_uint(f[3]);
                ph[mi][3] = prmt7632(u0, u1);
                h0 = __uint_as_float(u0 & 0xffff0000u); h1 = __uint_as_float(u1 & 0xffff0000u);
                pl[mi][3] = pkbf16x2(f[2] - h0, f[3] - h1);
            }
#pragma unroll
            for (int db = 0; db < 4; db++) {
                const uint32_t voff = ((kk * 16 + (lane & 15)) * LDS + db * 16 + (lane >> 4) * 8) * 2;
                uint32_t th[4], tl[4];
                ldsm_x4_t(th, uVh + voff);
                ldsm_x4_t(tl, uVl + voff);
#pragma unroll
                for (int mi = 0; mi < 2; mi++) {
                    mma_bf16(accO[mi][2 * db],     ph[mi], th);
                    mma_bf16(accO[mi][2 * db + 1], ph[mi], th + 2);
                    mma_bf16(accO[mi][2 * db],     ph[mi], tl);
                    mma_bf16(accO[mi][2 * db + 1], ph[mi], tl + 2);
                    mma_bf16(accO[mi][2 * db],     pl[mi], th);
                    mma_bf16(accO[mi][2 * db + 1], pl[mi], th + 2);
                }
            }
        }
    }

#pragma unroll
    for (int off = 1; off <= 2; off <<= 1) {
#pragma unroll
        for (int mi = 0; mi < 2; mi++) {
            l[mi][0] += __shfl_xor_sync(0xffffffffu, l[mi][0], off);
            l[mi][1] += __shfl_xor_sync(0xffffffffu, l[mi][1], off);
        }
    }

#pragma unroll
    for (int mi = 0; mi < 2; mi++) {
        float inv0 = rcp_fma(l[mi][0]), inv1 = rcp_fma(l[mi][1]);
        size_t ro = (tokq + w * 32 + mi * 16 + g) * CE + h * CD;
#pragma unroll
        for (int ni = 0; ni < 8; ni++) {
            int c = ni * 8 + tg * 2;
            *(uint32_t*)&Ohm[ro + c] =
                pkf16x2(accO[mi][ni][0] * inv0, accO[mi][ni][1] * inv0);
            *(uint32_t*)&Ohm[ro + 8 * CE + c] =
                pkf16x2(accO[mi][ni][2] * inv1, accO[mi][ni][3] * inv1);
        }
    }
}

// ---------------------------------------------------------------------------
extern "C" void kernel_launch(void* const* d_in, const int* in_sizes, int n_in,
                              void* d_out, int out_size)
{
    (void)in_sizes; (void)n_in; (void)out_size;
    const float* query = (const float*)d_in[0];
    const float* Wq    = (const float*)d_in[1];
    const float* bq    = (const float*)d_in[2];
    const float* Wk    = (const float*)d_in[3];
    const float* bk    = (const float*)d_in[4];
    const float* Wv    = (const float*)d_in[5];
    const float* bv    = (const float*)d_in[6];
    const float* Wo    = (const float*)d_in[7];
    const float* bo    = (const float*)d_in[8];
    const float* alpha = (const float*)d_in[9];

    float *qn, *kn;
    cudaGetSymbolAddress((void**)&qn, g_qn);
    cudaGetSymbolAddress((void**)&kn, g_kn);
    __half *xh, *xl, *oh, *wqh, *wql, *wkh, *wkl, *wvh, *wvl, *woh, *wol;
    __half *aqh, *aql, *akh, *akl;
    __nv_bfloat16 *avh, *avl;
    cudaGetSymbolAddress((void**)&xh, g_xh);   cudaGetSymbolAddress((void**)&xl, g_xl);
    cudaGetSymbolAddress((void**)&oh, g_oh);
    cudaGetSymbolAddress((void**)&wqh, g_wqh); cudaGetSymbolAddress((void**)&wql, g_wql);
    cudaGetSymbolAddress((void**)&wkh, g_wkh); cudaGetSymbolAddress((void**)&wkl, g_wkl);
    cudaGetSymbolAddress((void**)&wvh, g_wvh); cudaGetSymbolAddress((void**)&wvl, g_wvl);
    cudaGetSymbolAddress((void**)&woh, g_woh); cudaGetSymbolAddress((void**)&wol, g_wol);
    cudaGetSymbolAddress((void**)&aqh, g_aqh); cudaGetSymbolAddress((void**)&aql, g_aql);
    cudaGetSymbolAddress((void**)&akh, g_akh); cudaGetSymbolAddress((void**)&akl, g_akl);
    cudaGetSymbolAddress((void**)&avh, g_avh); cudaGetSymbolAddress((void**)&avl, g_avl);

    const int nx4 = CM * CE / 4;       // 1048576
    const int nw4 = CE * CE / 4;       // 262144
    {
        SplitJob jx = {query, xh, xl};
        SplitJob jq = {Wq, wqh, wql}, jk = {Wk, wkh, wkl}, jv = {Wv, wvh, wvl}, jo = {Wo, woh, wol};
        prep_all<<<dim3(nx4 / 256, 5), 256>>>(jx, jq, jk, jv, jo, qn, kn, nx4, nw4);
    }

    cudaFuncSetAttribute(hgemm_nt_mixed, cudaFuncAttributeMaxDynamicSharedMemorySize, HG_SMEM);
    {
        // Q,K: fp16 3-product (exp-amplified path). V: fp16 2-product (linear).
        GemmJob jq = {xh, xl, wqh, wql, bq, nullptr, aqh, aql, qn, 1, 1};
        GemmJob jk = {xh, xl, wkh, wkl, bk, nullptr, akh, akl, kn, 1, 1};
        GemmJob jv = {xh, xl, wvh, wvl, bv, nullptr, avh, avl, nullptr, 2, 0};
        hgemm_nt_mixed<<<dim3(CE / 128, CM / 128, 3), 256, HG_SMEM>>>(jq, jk, jv, CM, CE, CE);
    }

    cudaFuncSetAttribute(yat_attn_mma, cudaFuncAttributeMaxDynamicSharedMemorySize, ATTN_SMEM);
    yat_attn_mma<<<dim3(CS / 256, CH, CB), 256, ATTN_SMEM>>>(
        aqh, aql, akh, akl, avh, avl, qn, kn, oh, alpha);

    {
        // Output projection: fp16 2-product (linear path)
        GemmJob jo = {oh, nullptr, woh, wol, bo, (float*)d_out, nullptr, nullptr, nullptr, 0, 0};
        hgemm_nt_mixed<<<dim3(CE / 128, CM / 128, 1), 256, HG_SMEM>>>(jo, jo, jo, CM, CE, CE);
    }
}